// round 15
// baseline (speedup 1.0000x reference)
#include <cuda_runtime.h>
#include <cuda.h>
#include <cuda_bf16.h>
#include <math.h>
#include <stdint.h>

#define NTOK 4096
#define TT   2048
#define CC   1024
#define HH   16
#define HD   64
#define EE   8
#define CAPX 1024
#define HID  4096

#if defined(__CUDA_ARCH__)
# if (__CUDA_ARCH__ >= 1000) && (defined(__CUDA_ARCH_FEAT_SM103_ALL) || defined(__CUDA_ARCH_FEAT_SM100_ALL) || defined(__CUDA_ARCH_SPECIFIC__) || defined(__CUDA_ARCH_FAMILY_SPECIFIC__))
#  define USE_TC 1
# else
#  define USE_TC 0
# endif
#else
# define USE_TC 0
#endif

typedef __nv_bfloat16 bf16;
typedef __nv_bfloat162 bf162;

// PDL: wait for upstream grid completion + memory flush before touching data.
__device__ __forceinline__ void pdl_sync() {
#if defined(__CUDA_ARCH__) && (__CUDA_ARCH__ >= 900)
    cudaGridDependencySynchronize();
#endif
}

// ---------------- scratch ----------------
__device__ float g_xmix[(size_t)NTOK*CC];
__device__ float g_h   [(size_t)NTOK*CC];
__device__ float g_g0  [NTOK];
__device__ int   g_eid [NTOK];
__device__ int   g_idx [EE*CAPX];
__device__ int   g_cnt [EE];
__device__ float g_rotc[TT*16];
__device__ float g_rots[TT*16];
__device__ bf16 g_abf [2][(size_t)NTOK*CC];
__device__ bf16 g_obf [2][(size_t)NTOK*CC];
__device__ bf16 g_hbf [2][(size_t)NTOK*CC];
__device__ bf16 g_qbf [2][(size_t)NTOK*CC];      // [bh][t][d]
__device__ bf16 g_kbf [2][(size_t)NTOK*CC];      // [bh][t][d]
__device__ bf16 g_vT  [2][(size_t)NTOK*CC];      // [bh][d][t]
__device__ __align__(256) bf16 g_h1bf[2][(size_t)EE*CAPX*HID];
__device__ __align__(256) bf16 g_wqkv[2][(size_t)3*CC*CC];
__device__ __align__(256) bf16 g_wcp [2][(size_t)CC*CC];
__device__ __align__(256) bf16 g_we1 [2][(size_t)EE*HID*CC];
__device__ __align__(256) bf16 g_we2 [2][(size_t)EE*CC*HID];

__constant__ float c_rotinv[16] = {
    1.0f, 0.6299605249474366f, 0.39685026299204984f, 0.25f,
    0.15749013123685915f, 0.09921256574801246f, 0.0625f, 0.03937253280921479f,
    0.024803141437003115f, 0.015625f, 0.009843133202303697f, 0.0062007853592507785f,
    0.00390625f, 0.0024607833005759242f, 0.0015501963398126947f, 0.0009765625f
};

// ---------------- helpers ----------------
__device__ __forceinline__ uint32_t smem_u32(const void* p) {
    uint32_t a;
    asm("{ .reg .u64 t; cvta.to.shared.u64 t, %1; cvt.u32.u64 %0, t; }" : "=r"(a) : "l"(p));
    return a;
}
__device__ __forceinline__ uint32_t sw128(uint32_t off) { return off ^ ((off >> 3) & 0x70); }

__device__ __forceinline__ void cpa16(uint32_t d, const void* s) {
    asm volatile("cp.async.cg.shared.global [%0], [%1], 16;" :: "r"(d), "l"(s) : "memory");
}
#define CPA_COMMIT() asm volatile("cp.async.commit_group;" ::: "memory")
#define CPA_WAIT(n)  asm volatile("cp.async.wait_group %0;" :: "n"(n) : "memory")

__device__ __forceinline__ void split4(float4 v, uint2& hv, uint2& lv) {
    bf16 h0 = __float2bfloat16_rn(v.x), h1 = __float2bfloat16_rn(v.y);
    bf16 h2 = __float2bfloat16_rn(v.z), h3 = __float2bfloat16_rn(v.w);
    bf162 hp0; hp0.x = h0; hp0.y = h1;
    bf162 hp1; hp1.x = h2; hp1.y = h3;
    bf162 lp0 = __floats2bfloat162_rn(v.x - __bfloat162float(h0), v.y - __bfloat162float(h1));
    bf162 lp1 = __floats2bfloat162_rn(v.z - __bfloat162float(h2), v.w - __bfloat162float(h3));
    hv.x = *(uint32_t*)&hp0; hv.y = *(uint32_t*)&hp1;
    lv.x = *(uint32_t*)&lp0; lv.y = *(uint32_t*)&lp1;
}

#if USE_TC
__device__ __forceinline__ uint32_t elect_one() {
    uint32_t p;
    asm volatile("{\n\t.reg .pred p;\n\telect.sync _|p, 0xFFFFFFFF;\n\tselp.b32 %0, 1, 0, p;\n\t}" : "=r"(p));
    return p;
}
__device__ __forceinline__ uint32_t ctarank() {
    uint32_t r;
    asm("mov.u32 %0, %%cluster_ctarank;" : "=r"(r));
    return r;
}
#define CLUSTER_SYNC() do { \
    asm volatile("barrier.cluster.arrive.aligned;" ::: "memory"); \
    asm volatile("barrier.cluster.wait.aligned;" ::: "memory"); \
} while (0)
#define MBAR_INIT(addr, cnt) \
    asm volatile("mbarrier.init.shared.b64 [%0], %1;" :: "r"(addr), "r"(cnt) : "memory")
#define MBAR_EXPECT_TX(addr, bytes) \
    asm volatile("mbarrier.arrive.expect_tx.shared.b64 _, [%0], %1;" :: "r"(addr), "r"(bytes) : "memory")
__device__ __forceinline__ void mbar_wait(uint32_t addr, int phase) {
    uint32_t done = 0;
    while (!done) {
        asm volatile("{\n\t.reg .pred p;\n\t"
            "mbarrier.try_wait.parity.acquire.cta.shared::cta.b64 p, [%1], %2, 0x989680;\n\t"
            "selp.b32 %0, 1, 0, p;\n\t}" : "=r"(done) : "r"(addr), "r"(phase) : "memory");
    }
}
#define TMA_MC_3D(smem, map, x, y, zc, mbar, mask) \
    asm volatile("cp.async.bulk.tensor.3d.shared::cluster.global.tile.mbarrier::complete_tx::bytes.multicast::cluster " \
        "[%0], [%1, {%2, %3, %4}], [%5], %6;" \
        :: "r"(smem), "l"(map), "r"(x), "r"(y), "r"(zc), "r"(mbar), "h"((uint16_t)(mask)) : "memory")
#define TC_ALLOC(addr, n) \
    asm volatile("tcgen05.alloc.cta_group::1.sync.aligned.shared::cta.b32 [%0], %1;" :: "r"(addr), "r"(n) : "memory")
#define TC_DEALLOC(tm, n) \
    asm volatile("tcgen05.dealloc.cta_group::1.sync.aligned.b32 %0, %1;" :: "r"(tm), "r"(n))
#define TC_RELINQ() \
    asm volatile("tcgen05.relinquish_alloc_permit.cta_group::1.sync.aligned;")
#define TC_COMMIT(mbar) \
    asm volatile("tcgen05.commit.cta_group::1.mbarrier::arrive::one.shared::cluster.b64 [%0];" :: "r"(mbar) : "memory")
#define TC_COMMIT_MC(mbar, mask) \
    asm volatile("tcgen05.commit.cta_group::1.mbarrier::arrive::one.shared::cluster.multicast::cluster.b64 [%0], %1;" \
        :: "r"(mbar), "h"((uint16_t)(mask)) : "memory")
#define TC_FENCE_AFTER()  asm volatile("tcgen05.fence::after_thread_sync;" ::: "memory")
#define TC_FENCE_BEFORE() asm volatile("tcgen05.fence::before_thread_sync;" ::: "memory")
#define TC_WAIT_LD()      asm volatile("tcgen05.wait::ld.sync.aligned;" ::: "memory")
#define TC_WAIT_ST()      asm volatile("tcgen05.wait::st.sync.aligned;" ::: "memory")

#define TC_LD_X32(r, a) \
    asm volatile("tcgen05.ld.sync.aligned.32x32b.x32.b32 " \
        "{%0,%1,%2,%3,%4,%5,%6,%7,%8,%9,%10,%11,%12,%13,%14,%15," \
        "%16,%17,%18,%19,%20,%21,%22,%23,%24,%25,%26,%27,%28,%29,%30,%31}, [%32];" \
        : "=r"((r)[0]),"=r"((r)[1]),"=r"((r)[2]),"=r"((r)[3]),"=r"((r)[4]),"=r"((r)[5]),"=r"((r)[6]),"=r"((r)[7]), \
          "=r"((r)[8]),"=r"((r)[9]),"=r"((r)[10]),"=r"((r)[11]),"=r"((r)[12]),"=r"((r)[13]),"=r"((r)[14]),"=r"((r)[15]), \
          "=r"((r)[16]),"=r"((r)[17]),"=r"((r)[18]),"=r"((r)[19]),"=r"((r)[20]),"=r"((r)[21]),"=r"((r)[22]),"=r"((r)[23]), \
          "=r"((r)[24]),"=r"((r)[25]),"=r"((r)[26]),"=r"((r)[27]),"=r"((r)[28]),"=r"((r)[29]),"=r"((r)[30]),"=r"((r)[31]) \
        : "r"(a))

#define TC_ST_X32(a, r) \
    asm volatile("tcgen05.st.sync.aligned.32x32b.x32.b32 [%0], " \
        "{%1,%2,%3,%4,%5,%6,%7,%8,%9,%10,%11,%12,%13,%14,%15,%16," \
        "%17,%18,%19,%20,%21,%22,%23,%24,%25,%26,%27,%28,%29,%30,%31,%32};" \
        :: "r"(a), \
           "r"((r)[0]),"r"((r)[1]),"r"((r)[2]),"r"((r)[3]),"r"((r)[4]),"r"((r)[5]),"r"((r)[6]),"r"((r)[7]), \
           "r"((r)[8]),"r"((r)[9]),"r"((r)[10]),"r"((r)[11]),"r"((r)[12]),"r"((r)[13]),"r"((r)[14]),"r"((r)[15]), \
           "r"((r)[16]),"r"((r)[17]),"r"((r)[18]),"r"((r)[19]),"r"((r)[20]),"r"((r)[21]),"r"((r)[22]),"r"((r)[23]), \
           "r"((r)[24]),"r"((r)[25]),"r"((r)[26]),"r"((r)[27]),"r"((r)[28]),"r"((r)[29]),"r"((r)[30]),"r"((r)[31]) \
        : "memory")

__device__ __forceinline__ void mma_ss_bf16(uint32_t d, uint64_t ad, uint64_t bd,
                                            uint32_t idesc, uint32_t en) {
    asm volatile("{\n\t.reg .pred p;\n\tsetp.ne.u32 p, %4, 0;\n\t"
        "tcgen05.mma.cta_group::1.kind::f16 [%0], %1, %2, %3, {%5,%5,%5,%5}, p;\n\t}"
        :: "r"(d), "l"(ad), "l"(bd), "r"(idesc), "r"(en), "r"(0u) : "memory");
}
__device__ __forceinline__ void mma_ts_bf16(uint32_t d, uint32_t a, uint64_t bd,
                                            uint32_t idesc, uint32_t en) {
    asm volatile("{\n\t.reg .pred p;\n\tsetp.ne.u32 p, %4, 0;\n\t"
        "tcgen05.mma.cta_group::1.kind::f16 [%0], [%1], %2, %3, {%5,%5,%5,%5}, p;\n\t}"
        :: "r"(d), "r"(a), "l"(bd), "r"(idesc), "r"(en), "r"(0u) : "memory");
}
__device__ __forceinline__ uint64_t make_desc(uint32_t base) {
    const uint64_t B = (uint64_t(2) << 61) | (uint64_t(1) << 46) | (uint64_t(64) << 32) | (uint64_t(1) << 16);
    return B | ((uint64_t)(base >> 4) & 0x3FFF);
}
#endif // USE_TC

// ---------------- rotary tables ----------------
__global__ void rot_tab_kernel() {
    int idx = blockIdx.x * 256 + threadIdx.x;
    if (idx >= TT * 16) return;
    int t = idx >> 4, j = idx & 15;
    float th = (float)t * c_rotinv[j];
    g_rotc[idx] = cosf(th);
    g_rots[idx] = sinf(th);
}

// ---------------- fp32 -> hi/lo bf16 ----------------
__global__ void conv_kernel(const float* __restrict__ src, bf16* __restrict__ hi,
                            bf16* __restrict__ lo, long n4) {
    long i = (long)blockIdx.x * blockDim.x + threadIdx.x;
    if (i >= n4) return;
    float4 v = ((const float4*)src)[i];
    uint2 hv, lv; split4(v, hv, lv);
    ((uint2*)hi)[i] = hv; ((uint2*)lo)[i] = lv;
}

// ======= bf16 GEMM: 128x256 tile, 3-term split, cluster-2 B TMA-multicast =======
// EPI: 1=+bias 2=+bias+resid 3=sq(relu(+bias)) 4=scatter 5=fused qk-rot / V-transpose
#define A_PL 16384
#define B_PL 32768
#define BUF_BYTES 98304
#define SMEM_TOTAL_TC (1024 + 2*BUF_BYTES)

template<int EPI, bool GATHER, bool SKIP>
__global__ __launch_bounds__(256)
void gemm_bf(const bf16* __restrict__ Ahi, const bf16* __restrict__ Alo, long aStride,
             const bf16* __restrict__ Bhi, const bf16* __restrict__ Blo, long bStride,
             const __grid_constant__ CUtensorMap tmBh,
             const __grid_constant__ CUtensorMap tmBl,
             float* __restrict__ Cf, bf16* __restrict__ Chi, bf16* __restrict__ Clo, long cStride,
             const float* __restrict__ bias, int biasStride,
             const float* __restrict__ resid,
             const int* __restrict__ rowIdx,
             const int* __restrict__ counts,
             const float* __restrict__ g0,
             int Nt, int Kd) {
    extern __shared__ char smem[];
    pdl_sync();   // upstream data (A, rowIdx/counts, resid) fully visible
    const int z = blockIdx.z;
    const int m0 = blockIdx.y * 128, n0 = blockIdx.x * 256;
    int cnt = 0;
    if (SKIP) {
        cnt = counts[z];
        int pairBase = (int)(blockIdx.y & ~1u) * 128;   // pair-level skip (cluster lockstep)
        if (pairBase >= cnt) return;
    }
    bool active = !SKIP || (m0 < cnt);
    int tid = threadIdx.x, wid = tid >> 5, lane = tid & 31;

    const uint32_t OFF_MB = 8, OFF_RID = 64, OFF_TILE = 1024;
    int* s_rid = (int*)(smem + OFF_RID);
    if (tid < 128) {
        int r;
        if (GATHER) r = min(rowIdx[z * CAPX + m0 + tid], NTOK - 1);
        else        r = m0 + tid;
        s_rid[tid] = r;
    }
    const bf16* Ahz = Ahi + (size_t)z * aStride;
    const bf16* Alz = Alo + (size_t)z * aStride;

#if USE_TC
    uint32_t sbase = smem_u32(smem);
    uint32_t rank = ctarank();
    const uint32_t MB0 = sbase + OFF_MB,      MB1 = sbase + OFF_MB + 8;
    const uint32_t BB0 = sbase + OFF_MB + 16, BB1 = sbase + OFF_MB + 24;
    if (tid == 0) {
        MBAR_INIT(MB0, 2); MBAR_INIT(MB1, 2);
        MBAR_INIT(BB0, 1); MBAR_INIT(BB1, 1);
    }
    if (wid == 0) { TC_ALLOC(sbase + 0, 256u); }
    __syncthreads();
    CLUSTER_SYNC();
    uint32_t tmem = *(uint32_t*)(smem + 0);

    const uint32_t idesc = (1u << 4) | (1u << 7) | (1u << 10) | (32u << 17) | (8u << 24); // N=256

    int nchunks = Kd >> 6;

    auto issue_A = [&](int c, uint32_t tb) {
        int k0 = c * 64;
        #pragma unroll
        for (int i = 0; i < 4; i++) {
            int f = tid + i * 256;
            int row = f >> 3, c8 = f & 7;
            uint32_t so = sw128((uint32_t)(row * 128 + c8 * 16));
            size_t aoff = (size_t)s_rid[row] * Kd + k0 + c8 * 8;
            cpa16(tb + so,        Ahz + aoff);
            cpa16(tb + A_PL + so, Alz + aoff);
        }
        CPA_COMMIT();
    };
    auto issue_B = [&](int c, int buf) {
        if (tid != 0) return;
        uint32_t tb = sbase + OFF_TILE + (uint32_t)buf * BUF_BYTES;
        uint32_t bb = buf ? BB1 : BB0;
        MBAR_EXPECT_TX(bb, 65536u);
        uint32_t soff = rank ? 16384u : 0u;
        int k0 = c * 64;
        int ycoord = n0 + (int)rank * 128;
        TMA_MC_3D(tb + 2 * A_PL + soff,        &tmBh, k0, ycoord, z, bb, 3);
        TMA_MC_3D(tb + 2 * A_PL + B_PL + soff, &tmBl, k0, ycoord, z, bb, 3);
    };

    issue_A(0, sbase + OFF_TILE);
    issue_B(0, 0);

    int ph0 = 0, ph1 = 0, pb0 = 0, pb1 = 0;

    for (int c = 0; c < nchunks; c++) {
        int buf = c & 1;
        uint32_t tb = sbase + OFF_TILE + buf * BUF_BYTES;
        if (c + 1 < nchunks) {
            if (c >= 1) {
                if ((buf ^ 1) == 0) { mbar_wait(MB0, ph0); ph0 ^= 1; }
                else                { mbar_wait(MB1, ph1); ph1 ^= 1; }
            }
            issue_A(c + 1, sbase + OFF_TILE + (buf ^ 1) * BUF_BYTES);
            issue_B(c + 1, buf ^ 1);
            CPA_WAIT(1);
        } else {
            CPA_WAIT(0);
        }
        if (buf == 0) { mbar_wait(BB0, pb0); pb0 ^= 1; }
        else          { mbar_wait(BB1, pb1); pb1 ^= 1; }
        asm volatile("fence.proxy.async.shared::cta;" ::: "memory");
        __syncthreads();
        if (wid == 0) {
            if (elect_one()) {
                uint64_t ah = make_desc(tb);
                uint64_t al = make_desc(tb + A_PL);
                uint64_t bh = make_desc(tb + 2 * A_PL);
                uint64_t bl = make_desc(tb + 2 * A_PL + B_PL);
                #pragma unroll
                for (int ks = 0; ks < 4; ks++) {
                    uint64_t o = ks * 2;
                    mma_ss_bf16(tmem, ah + o, bh + o, idesc, (c > 0 || ks > 0) ? 1u : 0u);
                    mma_ss_bf16(tmem, ah + o, bl + o, idesc, 1u);
                    mma_ss_bf16(tmem, al + o, bh + o, idesc, 1u);
                }
                TC_COMMIT_MC(buf == 0 ? MB0 : MB1, 3);
            }
        }
    }
    mbar_wait(MB0, ph0);
    mbar_wait(MB1, ph1);
    TC_FENCE_AFTER();
    CLUSTER_SYNC();

    int colbase = (wid >> 2) * 128;
    int row = (wid & 3) * 32 + lane;
    int gm = m0 + row;

    if (EPI == 5) {
        if (z < 2) {
            int t = gm & (TT - 1), bb = gm >> 11;
            bf16* hip = z ? g_kbf[0] : g_qbf[0];
            bf16* lop = z ? g_kbf[1] : g_qbf[1];
            const float* ctab = g_rotc + t * 16;
            const float* stab = g_rots + t * 16;
            float cv[16], sv[16];
            #pragma unroll
            for (int d = 0; d < 16; d += 4) {
                float4 c4 = *(const float4*)(ctab + d);
                float4 s4 = *(const float4*)(stab + d);
                cv[d] = c4.x; cv[d+1] = c4.y; cv[d+2] = c4.z; cv[d+3] = c4.w;
                sv[d] = s4.x; sv[d+1] = s4.y; sv[d+2] = s4.z; sv[d+3] = s4.w;
            }
            #pragma unroll
            for (int g2 = 0; g2 < 2; g2++) {
                int co = colbase + g2 * 64;
                uint32_t dr[64];
                TC_LD_X32(dr,      tmem + co);
                TC_LD_X32(dr + 32, tmem + co + 32);
                TC_WAIT_LD();
                float v[64]; float ss = 0.f;
                #pragma unroll
                for (int j = 0; j < 64; j++) { v[j] = __uint_as_float(dr[j]); ss += v[j] * v[j]; }
                float sc = rsqrtf(ss * (1.0f / HD) + 1e-6f);
                float o[64];
                #pragma unroll
                for (int d = 0; d < 16; d++) {
                    float x1 = v[d] * sc, x2 = v[d + 32] * sc;
                    o[d]      =  x1 * cv[d] + x2 * sv[d];
                    o[d + 32] = -x1 * sv[d] + x2 * cv[d];
                }
                #pragma unroll
                for (int d = 16; d < 32; d++) {
                    o[d]      = v[d] * sc;
                    o[d + 32] = v[d + 32] * sc;
                }
                int hh = (n0 + co) >> 6;
                size_t basep = ((size_t)(bb * HH + hh) * TT + t) * HD;
                #pragma unroll
                for (int j = 0; j < 64; j += 4) {
                    float4 f4; f4.x = o[j]; f4.y = o[j+1]; f4.z = o[j+2]; f4.w = o[j+3];
                    uint2 hv, lv; split4(f4, hv, lv);
                    *(uint2*)(hip + basep + j) = hv;
                    *(uint2*)(lop + basep + j) = lv;
                }
            }
        } else {
            const int TP = 136;
            bf16* sh = (bf16*)(smem + OFF_TILE);
            __syncthreads();
            #pragma unroll
            for (int g2 = 0; g2 < 2; g2++) {
                int co = colbase + g2 * 64;
                uint32_t dr[64];
                TC_LD_X32(dr,      tmem + co);
                TC_LD_X32(dr + 32, tmem + co + 32);
                TC_WAIT_LD();
                #pragma unroll
                for (int j = 0; j < 64; j++) {
                    float vv = __uint_as_float(dr[j]);
                    bf16 hv = __float2bfloat16_rn(vv);
                    bf16 lv = __float2bfloat16_rn(vv - __bfloat162float(hv));
                    sh[(size_t)(co + j) * TP + row]       = hv;
                    sh[(size_t)(256 + co + j) * TP + row] = lv;
                }
            }
            __syncthreads();
            int bb2 = m0 >> 11, t0 = m0 & (TT - 1);
            int col = n0 + tid;
            int hh = col >> 6, dd = col & 63;
            size_t dst = ((size_t)((bb2 * HH + hh) * HD + dd)) * TT + t0;
            const bf16* s0 = sh + (size_t)tid * TP;
            const bf16* s1 = sh + (size_t)(256 + tid) * TP;
            #pragma unroll
            for (int q = 0; q < 128; q += 8) {
                *(uint4*)(g_vT[0] + dst + q) = *(const uint4*)(s0 + q);
                *(uint4*)(g_vT[1] + dst + q) = *(const uint4*)(s1 + q);
            }
        }
    } else {
        int token = 0; float gg = 0.f; bool valid4 = active;
        if (EPI == 4) {
            valid4 = active && (gm < cnt);
            if (valid4) { token = rowIdx[z * CAPX + gm]; gg = g0[token]; }
        }
        #pragma unroll
        for (int g2 = 0; g2 < 2; g2++) {
            int co = colbase + g2 * 64;
            uint32_t dr[64];
            TC_LD_X32(dr,      tmem + co);
            TC_LD_X32(dr + 32, tmem + co + 32);
            TC_WAIT_LD();

            const float* bp = (EPI >= 1) ? (bias + (size_t)z * biasStride + n0 + co) : nullptr;
            if (EPI == 3) {
                if (active) {
                    bf16* chp = Chi + (size_t)z * cStride + (size_t)gm * Nt + n0 + co;
                    bf16* clp = Clo + (size_t)z * cStride + (size_t)gm * Nt + n0 + co;
                    #pragma unroll
                    for (int j = 0; j < 64; j += 4) {
                        float4 v;
                        float t0 = __uint_as_float(dr[j+0]) + bp[j+0];
                        float t1 = __uint_as_float(dr[j+1]) + bp[j+1];
                        float t2 = __uint_as_float(dr[j+2]) + bp[j+2];
                        float t3 = __uint_as_float(dr[j+3]) + bp[j+3];
                        v.x = t0 > 0.f ? t0*t0 : 0.f; v.y = t1 > 0.f ? t1*t1 : 0.f;
                        v.z = t2 > 0.f ? t2*t2 : 0.f; v.w = t3 > 0.f ? t3*t3 : 0.f;
                        uint2 hv, lv; split4(v, hv, lv);
                        *(uint2*)(chp + j) = hv; *(uint2*)(clp + j) = lv;
                    }
                }
            } else if (EPI == 4) {
                if (valid4) {
                    float* op = Cf + (size_t)token * Nt + n0 + co;
                    #pragma unroll
                    for (int j = 0; j < 64; j += 4) {
                        float4 o = *(float4*)(op + j);
                        o.x += gg * (__uint_as_float(dr[j+0]) + bp[j+0]);
                        o.y += gg * (__uint_as_float(dr[j+1]) + bp[j+1]);
                        o.z += gg * (__uint_as_float(dr[j+2]) + bp[j+2]);
                        o.w += gg * (__uint_as_float(dr[j+3]) + bp[j+3]);
                        *(float4*)(op + j) = o;
                    }
                }
            } else {
                const float* rp = (EPI == 2) ? (resid + (size_t)gm * Nt + n0 + co) : nullptr;
                float* cp = Cf + (size_t)z * cStride + (size_t)gm * Nt + n0 + co;
                #pragma unroll
                for (int j = 0; j < 64; j += 4) {
                    float vv[4];
                    #pragma unroll
                    for (int q = 0; q < 4; q++) {
                        float t = __uint_as_float(dr[j + q]);
                        if (EPI == 1)      t += bp[j + q];
                        else if (EPI == 2) t += bp[j + q] + rp[j + q];
                        vv[q] = t;
                    }
                    float4 v4; v4.x = vv[0]; v4.y = vv[1]; v4.z = vv[2]; v4.w = vv[3];
                    *(float4*)(cp + j) = v4;
                }
            }
        }
    }

    TC_FENCE_BEFORE();
    __syncthreads();
    if (wid == 0) { TC_RELINQ(); TC_DEALLOC(tmem, 256u); }

#else  // SIMT fallback (non-arch-specific pass; never selected on GB300)
    const bf16* Bhz = Bhi + (size_t)z * bStride;
    const bf16* Blz = Blo + (size_t)z * bStride;
    float* As = (float*)(smem + OFF_TILE);
    float* Bs = (float*)(smem + OFF_TILE + 16 * 128 * 4);
    float* Stg = (float*)(smem + OFF_TILE + 32 * 128 * 4);
    __syncthreads();
    int tm = (tid >> 4) * 8, tn = (tid & 15) * 8;
    for (int nsub = 0; nsub < 2; nsub++) {
        int n0s = n0 + nsub * 128;
        float acc[8][8];
        #pragma unroll
        for (int i = 0; i < 8; i++)
            #pragma unroll
            for (int j = 0; j < 8; j++) acc[i][j] = 0.f;
        for (int k0 = 0; k0 < Kd; k0 += 16) {
            #pragma unroll
            for (int i = 0; i < 2; i++) {
                int f = tid + i * 256;
                int rw_ = f >> 2, c4 = (f & 3) * 4;
                #pragma unroll
                for (int q = 0; q < 4; q++) {
                    size_t ao = (size_t)s_rid[rw_] * Kd + k0 + c4 + q;
                    size_t bo = (size_t)(n0s + rw_) * Kd + k0 + c4 + q;
                    As[(c4+q)*128 + rw_] = __bfloat162float(Ahz[ao]) + __bfloat162float(Alz[ao]);
                    Bs[(c4+q)*128 + rw_] = __bfloat162float(Bhz[bo]) + __bfloat162float(Blz[bo]);
                }
            }
            __syncthreads();
            #pragma unroll
            for (int kk = 0; kk < 16; kk++) {
                float a_[8], b_[8];
                #pragma unroll
                for (int q = 0; q < 8; q++) { a_[q] = As[kk*128 + tm + q]; b_[q] = Bs[kk*128 + tn + q]; }
                #pragma unroll
                for (int i = 0; i < 8; i++)
                    #pragma unroll
                    for (int j = 0; j < 8; j++)
                        acc[i][j] += a_[i] * b_[j];
            }
            __syncthreads();
        }
        if (EPI == 5) {
            #pragma unroll
            for (int i = 0; i < 8; i++)
                #pragma unroll
                for (int j = 0; j < 8; j++)
                    Stg[(tm + i) * 132 + tn + j] = acc[i][j];
            __syncthreads();
            int r = tid >> 1, hseg = tid & 1;
            int gmr = m0 + r;
            int t = gmr & (TT - 1), bb = gmr >> 11;
            float v[64];
            #pragma unroll
            for (int j = 0; j < 64; j++) v[j] = Stg[r * 132 + hseg * 64 + j];
            int col0 = n0s + hseg * 64;
            int hh = col0 >> 6;
            if (z < 2) {
                float ss = 0.f;
                #pragma unroll
                for (int j = 0; j < 64; j++) ss += v[j] * v[j];
                float sc = rsqrtf(ss * (1.0f / HD) + 1e-6f);
                bf16* hip = z ? g_kbf[0] : g_qbf[0];
                bf16* lop = z ? g_kbf[1] : g_qbf[1];
                size_t basep = ((size_t)(bb * HH + hh) * TT + t) * HD;
                #pragma unroll
                for (int d = 0; d < 32; d++) {
                    float x1 = v[d] * sc, x2 = v[d + 32] * sc;
                    float cth = (d < 16) ? g_rotc[t * 16 + d] : 1.f;
                    float sth = (d < 16) ? g_rots[t * 16 + d] : 0.f;
                    float y1 = x1 * cth + x2 * sth;
                    float y2 = -x1 * sth + x2 * cth;
                    bf16 h1 = __float2bfloat16_rn(y1), h2 = __float2bfloat16_rn(y2);
                    hip[basep + d] = h1; hip[basep + d + 32] = h2;
                    lop[basep + d] = __float2bfloat16_rn(y1 - __bfloat162float(h1));
                    lop[basep + d + 32] = __float2bfloat16_rn(y2 - __bfloat162float(h2));
                }
            } else {
                #pragma unroll
                for (int d = 0; d < 64; d++) {
                    float vv = v[d];
                    bf16 hv = __float2bfloat16_rn(vv);
                    size_t dst = ((size_t)((bb * HH + hh) * HD + d)) * TT + t;
                    g_vT[0][dst] = hv;
                    g_vT[1][dst] = __float2bfloat16_rn(vv - __bfloat162float(hv));
                }
            }
            __syncthreads();
        } else {
            #pragma unroll
            for (int i = 0; i < 8; i++) {
                int gmr = m0 + tm + i;
                bool act = !SKIP || (m0 < cnt);
                #pragma unroll
                for (int j = 0; j < 8; j++) {
                    float t = acc[i][j];
                    int col = n0s + tn + j;
                    if (EPI >= 1 && EPI <= 4) t += bias[(size_t)z * biasStride + col];
                    if (EPI == 2) t += resid[(size_t)gmr * Nt + col];
                    if (EPI == 3) {
                        if (act) {
                            t = t > 0.f ? t * t : 0.f;
                            bf16 hv = __float2bfloat16_rn(t);
                            Chi[(size_t)z * cStride + (size_t)gmr * Nt + col] = hv;
                            Clo[(size_t)z * cStride + (size_t)gmr * Nt + col] = __float2bfloat16_rn(t - __bfloat162float(hv));
                        }
                    } else if (EPI == 4) {
                        if (act && gmr < cnt) {
                            int token = rowIdx[z * CAPX + gmr];
                            atomicAdd(&Cf[(size_t)token * Nt + col], g0[token] * t);
                        }
                    } else {
                        Cf[(size_t)z * cStride + (size_t)gmr * Nt + col] = t;
                    }
                }
            }
        }
    }
#endif
}

// ---------------- block reduce ----------------
__device__ __forceinline__ float blockReduceSum(float v) {
    __shared__ float sh[32];
    int lane = threadIdx.x & 31, w = threadIdx.x >> 5;
    #pragma unroll
    for (int o = 16; o; o >>= 1) v += __shfl_down_sync(0xffffffffu, v, o);
    if (lane == 0) sh[w] = v;
    __syncthreads();
    int nw = blockDim.x >> 5;
    if (w == 0) {
        v = (lane < nw) ? sh[lane] : 0.f;
        #pragma unroll
        for (int o = 16; o; o >>= 1) v += __shfl_down_sync(0xffffffffu, v, o);
        if (lane == 0) sh[0] = v;
    }
    __syncthreads();
    return sh[0];
}

// ---------------- 1) residual mix + rmsnorm ----------------
__global__ void mix_rms_kernel(const float* __restrict__ x, const float* __restrict__ x0,
                               const float* __restrict__ lambdas) {
    pdl_sync();
    int row = blockIdx.x;
    float l0 = lambdas[0], l1 = lambdas[1];
    size_t off = (size_t)row * CC + threadIdx.x * 4;
    float4 a = *(const float4*)(x + off);
    float4 b = *(const float4*)(x0 + off);
    float4 v;
    v.x = l0*a.x + l1*b.x; v.y = l0*a.y + l1*b.y;
    v.z = l0*a.z + l1*b.z; v.w = l0*a.w + l1*b.w;
    *(float4*)(g_xmix + off) = v;
    float ss = v.x*v.x + v.y*v.y + v.z*v.z + v.w*v.w;
    float tot = blockReduceSum(ss);
    float sc = rsqrtf(tot * (1.0f/CC) + 1e-6f);
    float4 o; o.x = v.x*sc; o.y = v.y*sc; o.z = v.z*sc; o.w = v.w*sc;
    uint2 hv, lv; split4(o, hv, lv);
    *(uint2*)(&g_abf[0][off]) = hv;
    *(uint2*)(&g_abf[1][off]) = lv;
}

// ---------------- 6) rmsnorm of x2 ----------------
__global__ void rms2_kernel(const float* __restrict__ src) {
    pdl_sync();
    int row = blockIdx.x;
    size_t off = (size_t)row * CC + threadIdx.x * 4;
    float4 v = *(const float4*)(src + off);
    float ss = v.x*v.x + v.y*v.y + v.z*v.z + v.w*v.w;
    float tot = blockReduceSum(ss);
    float sc = rsqrtf(tot * (1.0f/CC) + 1e-6f);
    float4 o; o.x = v.x*sc; o.y = v.y*sc; o.z = v.z*sc; o.w = v.w*sc;
    *(float4*)(g_h + off) = o;
    uint2 hv, lv; split4(o, hv, lv);
    *(uint2*)(&g_hbf[0][off]) = hv;
    *(uint2*)(&g_hbf[1][off]) = lv;
}

// ---------------- 4) pipelined tensor-core causal attention ----------------
#define AT_QHI 2048
#define AT_QLO (AT_QHI + 16384)
#define AT_KBUF 34816
#define AT_VBUF (AT_KBUF + 3*32768)
#define SMEM_ATT (AT_VBUF + 2*32768)
#define AT_L2 128

__global__ __launch_bounds__(256) void attn_tc() {
    extern __shared__ char smem[];
    int qtile = gridDim.x - 1 - blockIdx.x;   // LPT
    int bh = blockIdx.y;
    int b = bh >> 4, h = bh & 15;
    int q0 = qtile * 128;
    int tid = threadIdx.x, wid = tid >> 5, lane = tid & 31;
    int half = wid >> 2;
    int row = (wid & 3) * 32 + lane;

    const bf16* qh_g = g_qbf[0] + ((size_t)bh * TT + q0) * HD;
    const bf16* ql_g = g_qbf[1] + ((size_t)bh * TT + q0) * HD;

#if USE_TC
    uint32_t sbase = smem_u32(smem);
    const uint32_t MBS = sbase + 8, MBA = sbase + 16;
    float* l2s = (float*)(smem + AT_L2);
    if (tid == 0) { MBAR_INIT(MBS, 1); MBAR_INIT(MBA, 1); }
    if (wid == 0) { TC_ALLOC(sbase + 0, 512u); }   // independent prologue under PDL
    pdl_sync();                                    // qkv GEMM outputs now visible

    auto load_K = [&](int kt) {
        uint32_t kb = sbase + AT_KBUF + (uint32_t)(kt % 3) * 32768;
        const bf16* kh_g = g_kbf[0] + ((size_t)bh * TT + kt * 128) * HD;
        const bf16* kl_g = g_kbf[1] + ((size_t)bh * TT + kt * 128) * HD;
        #pragma unroll
        for (int i = 0; i < 4; i++) {
            int f = tid + i * 256;
            int r = f >> 3, c8 = f & 7;
            uint32_t so = sw128((uint32_t)(r * 128 + c8 * 16));
            cpa16(kb + so,         kh_g + (size_t)r * HD + c8 * 8);
            cpa16(kb + 16384 + so, kl_g + (size_t)r * HD + c8 * 8);
        }
    };
    auto load_V = [&](int kt) {
        uint32_t vb = sbase + AT_VBUF + (uint32_t)(kt & 1) * 32768;
        const bf16* vh_g = g_vT[0] + (size_t)bh * HD * TT + kt * 128;
        const bf16* vl_g = g_vT[1] + (size_t)bh * HD * TT + kt * 128;
        #pragma unroll
        for (int i = 0; i < 4; i++) {
            int f = tid + i * 256;
            int d = f >> 4, c16 = f & 15;
            uint32_t byte = (uint32_t)((d >> 3) * 1024 + (c16 >> 3) * 8192 + (d & 7) * 128 + (c16 & 7) * 16);
            uint32_t so = sw128(byte);
            cpa16(vb + so,         vh_g + (size_t)d * TT + c16 * 8);
            cpa16(vb + 16384 + so, vl_g + (size_t)d * TT + c16 * 8);
        }
    };

    {
        #pragma unroll
        for (int i = 0; i < 4; i++) {
            int f = tid + i * 256;
            int r = f >> 3, c8 = f & 7;
            uint32_t so = sw128((uint32_t)(r * 128 + c8 * 16));
            cpa16(sbase + AT_QHI + so, qh_g + (size_t)r * HD + c8 * 8);
            cpa16(sbase + AT_QLO + so, ql_g + (size_t)r * HD + c8 * 8);
        }
        load_K(0);
        load_V(0);
        CPA_COMMIT();
        if (qtile >= 1) { load_K(1); CPA_COMMIT(); }
    }
    __syncthreads();
    uint32_t tmem = *(uint32_t*)(smem + 0);
    const uint32_t S0 = 0, O_OFF = 256, P0 = 320;
    const uint32_t IDS = (1u<<4)|(1u<<7)|(1u<<10)|(16u<<17)|(8u<<24);  // N=128
    const uint32_t IDA = (1u<<4)|(1u<<7)|(1u<<10)|( 8u<<17)|(8u<<24);  // N=64

    CPA_WAIT(0);
    asm volatile("fence.proxy.async.shared::cta;" ::: "memory");
    __syncthreads();

    uint64_t qhd = make_desc(sbase + AT_QHI);
    uint64_t qld = make_desc(sbase + AT_QLO);

    auto issue_S = [&](int kt) {
        uint32_t kb = sbase + AT_KBUF + (uint32_t)(kt % 3) * 32768;
        uint64_t kh = make_desc(kb);
        uint64_t kl = make_desc(kb + 16384);
        uint32_t sd = tmem + S0 + (uint32_t)(kt & 1) * 128;
        #pragma unroll
        for (int ks = 0; ks < 4; ks++) {
            uint64_t o = ks * 2;
            mma_ss_bf16(sd, qhd + o, kh + o, IDS, ks > 0 ? 1u : 0u);
            mma_ss_bf16(sd, qhd + o, kl + o, IDS, 1u);
            mma_ss_bf16(sd, qld + o, kh + o, IDS, 1u);
        }
        TC_COMMIT(MBS);
    };

    if (wid == 0 && elect_one()) issue_S(0);

    float l = 0.f;
    int phS = 0, phA = 0;

    for (int kt = 0; kt <= qtile; kt++) {
        int sbuf = kt & 1;
        if (kt + 2 <= qtile) { load_K(kt + 2); CPA_COMMIT(); }
        mbar_wait(MBS, phS); phS ^= 1;
        TC_FENCE_AFTER();
        if (kt + 2 <= qtile) { CPA_WAIT(1); } else { CPA_WAIT(0); }
        asm volatile("fence.proxy.async.shared::cta;" ::: "memory");
        __syncthreads();
        if (kt < qtile && wid == 0) {
            if (elect_one()) { TC_FENCE_AFTER(); issue_S(kt + 1); }
        }

        uint32_t sr[64];
        TC_LD_X32(sr, tmem + S0 + sbuf * 128 + half * 64);
        TC_WAIT_LD();
        TC_LD_X32(sr + 32, tmem + S0 + sbuf * 128 + half * 64 + 32);

        int qg = q0 + row;
        int kbase = kt * 128 + half * 64;
        bool maskTile = (kt == qtile);
        uint32_t pw[32];
        float lacc = 0.f;
        #pragma unroll
        for (int j2 = 0; j2 < 16; j2++) {
            float s0v = __uint_as_float(sr[2*j2])   * 0.125f;
            float s1v = __uint_as_float(sr[2*j2+1]) * 0.125f;
            float p0 = __expf(s0v), p1 = __expf(s1v);
            if (maskTile) {
                if (kbase + 2*j2     > qg) p0 = 0.f;
                if (kbase + 2*j2 + 1 > qg) p1 = 0.f;
            }
            bf162 pb = __floats2bfloat162_rn(p0, p1);
            lacc += __bfloat162float(pb.x) + __bfloat162float(pb.y);
            pw[j2] = *(uint32_t*)&pb;
        }
        TC_WAIT_LD();
        #pragma unroll
        for (int j2 = 16; j2 < 32; j2++) {
            float s0v = __uint_as_float(sr[2*j2])   * 0.125f;
            float s1v = __uint_as_float(sr[2*j2+1]) * 0.125f;
            float p0 = __expf(s0v), p1 = __expf(s1v);
            if (maskTile) {
                if (kbase + 2*j2     > qg) p0 = 0.f;
                if (kbase + 2*j2 + 1 > qg) p1 = 0.f;
            }
            bf162 pb = __floats2bfloat162_rn(p0, p1);
            lacc += __bfloat162float(pb.x) + __bfloat162float(pb.y);
            pw[j2] = *(uint32_t*)&pb;
        }
        l += lacc;

        if (kt > 0) { mbar_wait(MBA, phA); phA ^= 1; }

        if (kt < qtile) { load_V(kt + 1); CPA_COMMIT(); }

        TC_ST_X32(tmem + P0 + sbuf * 64 + half * 32 + ((uint32_t)(wid & 3) << 21), pw);
        TC_WAIT_ST();
        TC_FENCE_BEFORE();
        __syncthreads();

        if (wid == 0 && elect_one()) {
            TC_FENCE_AFTER();
            uint32_t vb = sbase + AT_VBUF + (uint32_t)sbuf * 32768;
            uint64_t vh = make_desc(vb);
            uint64_t vl = make_desc(vb + 16384);
            #pragma unroll
            for (int ks = 0; ks < 8; ks++) {
                uint64_t vo = (uint64_t)((ks & 3) * 2 + (ks >> 2) * 512);
                uint32_t at = tmem + P0 + sbuf * 64 + ks * 8;
                mma_ts_bf16(tmem + O_OFF, at, vh + vo, IDA, (kt > 0 || ks > 0) ? 1u : 0u);
                mma_ts_bf16(tmem + O_OFF, at, vl + vo, IDA, 1u);
            }
            TC_COMMIT(MBA);
        }
    }
    mbar_wait(MBA, phA);
    TC_FENCE_AFTER();

    l2s[half * 128 + row] = l;
    __syncthreads();
    float inv = 1.f / (l2s[row] + l2s[128 + row]);

    uint32_t od[32];
    TC_LD_X32(od, tmem + O_OFF + half * 32);
    TC_WAIT_LD();
    int token = b * TT + q0 + row;
    bf16* ohp = g_obf[0] + (size_t)token * CC + h * HD + half * 32;
    bf16* olp = g_obf[1] + (size_t)token * CC + h * HD + half * 32;
    #pragma unroll
    for (int j = 0; j < 32; j += 4) {
        float4 v;
        v.x = __uint_as_float(od[j+0]) * inv;
        v.y = __uint_as_float(od[j+1]) * inv;
        v.z = __uint_as_float(od[j+2]) * inv;
        v.w = __uint_as_float(od[j+3]) * inv;
        uint2 hv, lv; split4(v, hv, lv);
        *(uint2*)(ohp + j) = hv; *(uint2*)(olp + j) = lv;
    }
    TC_FENCE_BEFORE();
    __syncthreads();
    if (wid == 0) { TC_RELINQ(); TC_DEALLOC(tmem, 512u); }

#else // SIMT fallback attention
    pdl_sync();
    for (int qq = tid; qq < 128; qq += 256) {
        int qg = q0 + qq;
        float q[HD], o[HD];
        #pragma unroll
        for (int d = 0; d < HD; d++) {
            q[d] = (__bfloat162float(qh_g[(size_t)qq*HD+d]) + __bfloat162float(ql_g[(size_t)qq*HD+d])) * 0.125f;
            o[d] = 0.f;
        }
        float l = 0.f;
        for (int k = 0; k <= qg; k++) {
            const bf16* kh_g = g_kbf[0] + ((size_t)bh * TT + k) * HD;
            const bf16* kl_g = g_kbf[1] + ((size_t)bh * TT + k) * HD;
            float s = 0.f;
            #pragma unroll
            for (int d = 0; d < HD; d++)
                s += q[d] * (__bfloat162float(kh_g[d]) + __bfloat162float(kl_g[d]));
            float p = __expf(s);
            l += p;
            #pragma unroll
            for (int d = 0; d < HD; d++) {
                size_t vo = ((size_t)bh * HD + d) * TT + k;
                o[d] += p * (__bfloat162float(g_vT[0][vo]) + __bfloat162float(g_vT[1][vo]));
            }
        }
        float inv = 1.f / l;
        int token = b * TT + qg;
        #pragma unroll
        for (int d = 0; d < HD; d++) {
            float v = o[d] * inv;
            bf16 hv = __float2bfloat16_rn(v);
            g_obf[0][(size_t)token * CC + h * HD + d] = hv;
            g_obf[1][(size_t)token * CC + h * HD + d] = __float2bfloat16_rn(v - __bfloat162float(hv));
        }
    }
#endif
}

// ---------------- 7) router ----------------
__global__ void router_kernel(const float* __restrict__ rw, const float* __restrict__ rb,
                              const float* __restrict__ nw, const float* __restrict__ nb,
                              const float* __restrict__ noise) {
    pdl_sync();
    int n = blockIdx.x;
    int w = threadIdx.x >> 5, lane = threadIdx.x & 31;
    const float* hr = g_h + (size_t)n * CC;
    const float* wr = rw + (size_t)w * CC;
    const float* wn = nw + (size_t)w * CC;
    float s1 = 0.f, s2 = 0.f;
    for (int c = lane * 4; c < CC; c += 128) {
        float4 hv = *(const float4*)(hr + c);
        float4 r4 = *(const float4*)(wr + c);
        float4 n4 = *(const float4*)(wn + c);
        s1 += hv.x*r4.x + hv.y*r4.y + hv.z*r4.z + hv.w*r4.w;
        s2 += hv.x*n4.x + hv.y*n4.y + hv.z*n4.z + hv.w*n4.w;
    }
    #pragma unroll
    for (int o = 16; o; o >>= 1) {
        s1 += __shfl_xor_sync(0xffffffffu, s1, o);
        s2 += __shfl_xor_sync(0xffffffffu, s2, o);
    }
    __shared__ float lg[8], nl[8];
    if (lane == 0) { lg[w] = s1 + rb[w]; nl[w] = s2 + nb[w]; }
    __syncthreads();
    if (threadIdx.x == 0) {
        float nv[8];
        #pragma unroll
        for (int e = 0; e < 8; e++) {
            float xn = nl[e];
            float sp = (xn > 20.f) ? xn : log1pf(expf(xn));
            nv[e] = lg[e] + noise[(size_t)n * EE + e] * sp;
        }
        int i0 = 0; float v0 = nv[0];
        #pragma unroll
        for (int e = 1; e < 8; e++) if (nv[e] > v0) { v0 = nv[e]; i0 = e; }
        float v1 = -1e30f;
        #pragma unroll
        for (int e = 0; e < 8; e++) if (e != i0 && nv[e] > v1) { v1 = nv[e]; }
        float e1 = expf(v1 - v0);
        g_g0[n] = 1.f / (1.f + e1);
        g_eid[n] = i0;
    }
}

// ---------------- 8) per-expert capacity lists ----------------
__global__ void build_idx_kernel() {
    pdl_sync();
    int w = threadIdx.x >> 5, lane = threadIdx.x & 31;
    int count = 0;
    for (int base = 0; base < NTOK; base += 32) {
        int t = base + lane;
        bool p = (g_eid[t] == w);
        unsigned msk = __ballot_sync(0xffffffffu, p);
        int pos = count + __popc(msk & ((1u << lane) - 1u));
        if (p && pos < CAPX) g_idx[w * CAPX + pos] = t;
        count += __popc(msk);
    }
    int c = min(count, CAPX);
    if (lane == 0) g_cnt[w] = c;
    for (int s = c + lane; s < CAPX; s += 32) g_idx[w * CAPX + s] = NTOK;
}

// ---------------- host: tensormap encode via driver entry point ----------------
typedef CUresult (*EncodeFn)(CUtensorMap*, CUtensorMapDataType, cuuint32_t, void*,
    const cuuint64_t*, const cuuint64_t*, const cuuint32_t*, const cuuint32_t*,
    CUtensorMapInterleave, CUtensorMapSwizzle, CUtensorMapL2promotion, CUtensorMapFloatOOBfill);

static EncodeFn get_encode_fn() {
    static EncodeFn fn = nullptr;
    if (!fn) {
        void* p = nullptr;
        cudaDriverEntryPointQueryResult q;
        cudaGetDriverEntryPointByVersion("cuTensorMapEncodeTiled", &p, 12000, cudaEnableDefault, &q);
        fn = (EncodeFn)p;
    }
    return fn;
}

static void mk_map(CUtensorMap* tm, void* base, uint64_t d0, uint64_t d1, uint64_t d2) {
    cuuint64_t dims[3]    = {(cuuint64_t)d0, (cuuint64_t)d1, (cuuint64_t)d2};
    cuuint64_t strides[2] = {(cuuint64_t)(d0 * 2), (cuuint64_t)(d0 * d1 * 2)};
    cuuint32_t box[3]     = {64u, 128u, 1u};
    cuuint32_t es[3]      = {1u, 1u, 1u};
    get_encode_fn()(tm, CU_TENSOR_MAP_DATA_TYPE_BFLOAT16, 3, base, dims, strides, box, es,
        CU_TENSOR_MAP_INTERLEAVE_NONE, CU_TENSOR_MAP_SWIZZLE_128B,
        CU_TENSOR_MAP_L2_PROMOTION_L2_128B, CU_TENSOR_MAP_FLOAT_OOB_FILL_NONE);
}

// ---------------- host launcher ----------------
extern "C" void kernel_launch(void* const* d_in, const int* in_sizes, int n_in,
                              void* d_out, int out_size) {
    const float* x        = (const float*)d_in[0];
    const float* x0       = (const float*)d_in[1];
    const float* noise    = (const float*)d_in[2];
    const float* lambdas  = (const float*)d_in[3];
    const float* qkv_w    = (const float*)d_in[5];
    const float* c_proj_w = (const float*)d_in[6];
    const float* c_proj_b = (const float*)d_in[7];
    const float* router_w = (const float*)d_in[8];
    const float* router_b = (const float*)d_in[9];
    const float* noise_w  = (const float*)d_in[10];
    const float* noise_b  = (const float*)d_in[11];
    const float* ew1      = (const float*)d_in[12];
    const float* eb1      = (const float*)d_in[13];
    const float* ew2      = (const float*)d_in[14];
    const float* eb2      = (const float*)d_in[15];
    float* out = (float*)d_out;

    void *p_xmix, *p_h, *p_idx, *p_cnt, *p_g0;
    void *p_abf, *p_obf, *p_hbf, *p_h1bf, *p_wqkv, *p_wcp, *p_we1, *p_we2;
    cudaGetSymbolAddress(&p_xmix, g_xmix);
    cudaGetSymbolAddress(&p_h,    g_h);
    cudaGetSymbolAddress(&p_idx,  g_idx);
    cudaGetSymbolAddress(&p_cnt,  g_cnt);
    cudaGetSymbolAddress(&p_g0,   g_g0);
    cudaGetSymbolAddress(&p_abf,  g_abf);
    cudaGetSymbolAddress(&p_obf,  g_obf);
    cudaGetSymbolAddress(&p_hbf,  g_hbf);
    cudaGetSymbolAddress(&p_h1bf, g_h1bf);
    cudaGetSymbolAddress(&p_wqkv, g_wqkv);
    cudaGetSymbolAddress(&p_wcp,  g_wcp);
    cudaGetSymbolAddress(&p_we1,  g_we1);
    cudaGetSymbolAddress(&p_we2,  g_we2);

    bf16* abf_h  = (bf16*)p_abf;   bf16* abf_l  = abf_h  + (size_t)NTOK*CC;
    bf16* obf_h  = (bf16*)p_obf;   bf16* obf_l  = obf_h  + (size_t)NTOK*CC;
    bf16* hbf_h  = (bf16*)p_hbf;   bf16* hbf_l  = hbf_h  + (size_t)NTOK*CC;
    bf16* h1_h   = (bf16*)p_h1bf;  bf16* h1_l   = h1_h   + (size_t)EE*CAPX*HID;
    bf16* wqkv_h = (bf16*)p_wqkv;  bf16* wqkv_l = wqkv_h + (size_t)3*CC*CC;
    bf16* wcp_h  = (bf16*)p_wcp;   bf16* wcp_l  = wcp_h  + (size_t)CC*CC;
    bf16* we1_h  = (bf16*)p_we1;   bf16* we1_l  = we1_h  + (size_t)EE*HID*CC;
    bf16* we2_h  = (bf16*)p_we2;   bf16* we2_l  = we2_h  + (size_t)EE*CC*HID;

    CUtensorMap tmQh, tmQl, tmCh, tmCl, tmE1h, tmE1l, tmE2h, tmE2l;
    mk_map(&tmQh,  wqkv_h, CC, CC, 3);
    mk_map(&tmQl,  wqkv_l, CC, CC, 3);
    mk_map(&tmCh,  wcp_h,  CC, CC, 1);
    mk_map(&tmCl,  wcp_l,  CC, CC, 1);
    mk_map(&tmE1h, we1_h,  CC, HID, EE);
    mk_map(&tmE1l, we1_l,  CC, HID, EE);
    mk_map(&tmE2h, we2_h,  HID, CC, EE);
    mk_map(&tmE2l, we2_l,  HID, CC, EE);

    cudaFuncSetAttribute(gemm_bf<5,false,false>, cudaFuncAttributeMaxDynamicSharedMemorySize, SMEM_TOTAL_TC);
    cudaFuncSetAttribute(gemm_bf<2,false,false>, cudaFuncAttributeMaxDynamicSharedMemorySize, SMEM_TOTAL_TC);
    cudaFuncSetAttribute(gemm_bf<3,true, true >, cudaFuncAttributeMaxDynamicSharedMemorySize, SMEM_TOTAL_TC);
    cudaFuncSetAttribute(gemm_bf<4,false,true >, cudaFuncAttributeMaxDynamicSharedMemorySize, SMEM_TOTAL_TC);
    cudaFuncSetAttribute(attn_tc, cudaFuncAttributeMaxDynamicSharedMemorySize, SMEM_ATT);

    // launch configs: cluster GEMM (cluster + PDL), plain PDL
    cudaLaunchAttribute gattr[2];
    gattr[0].id = cudaLaunchAttributeClusterDimension;
    gattr[0].val.clusterDim.x = 1; gattr[0].val.clusterDim.y = 2; gattr[0].val.clusterDim.z = 1;
    gattr[1].id = cudaLaunchAttributeProgrammaticStreamSerialization;
    gattr[1].val.programmaticStreamSerializationAllowed = 1;
    cudaLaunchConfig_t gcfg = {};
    gcfg.blockDim = dim3(256, 1, 1);
    gcfg.dynamicSmemBytes = SMEM_TOTAL_TC;
    gcfg.attrs = gattr;
    gcfg.numAttrs = 2;
    gcfg.stream = 0;

    cudaLaunchAttribute pattr[1];
    pattr[0].id = cudaLaunchAttributeProgrammaticStreamSerialization;
    pattr[0].val.programmaticStreamSerializationAllowed = 1;
    cudaLaunchConfig_t pcfg = {};
    pcfg.attrs = pattr;
    pcfg.numAttrs = 1;
    pcfg.stream = 0;

    // ---- side stream: rotary tables + deferred weight conversions
    cudaStream_t s2;
    cudaStreamCreateWithFlags(&s2, cudaStreamNonBlocking);
    cudaEvent_t evFork, evRot, evJoinCp, evJoinMoE;
    cudaEventCreateWithFlags(&evFork,    cudaEventDisableTiming);
    cudaEventCreateWithFlags(&evRot,     cudaEventDisableTiming);
    cudaEventCreateWithFlags(&evJoinCp,  cudaEventDisableTiming);
    cudaEventCreateWithFlags(&evJoinMoE, cudaEventDisableTiming);

    cudaEventRecord(evFork, 0);
    cudaStreamWaitEvent(s2, evFork, 0);

    rot_tab_kernel<<<(TT*16 + 255)/256, 256, 0, s2>>>();
    cudaEventRecord(evRot, s2);
    conv_kernel<<<(CC*CC/4 + 255)/256, 256, 0, s2>>>(c_proj_w, wcp_h, wcp_l, (long)CC*CC/4);
    cudaEventRecord(evJoinCp, s2);
    conv_kernel<<<((long)EE*HID*CC/4 + 255)/256, 256, 0, s2>>>(ew1, we1_h, we1_l, (long)EE*HID*CC/4);
    conv_kernel<<<((long)EE*CC*HID/4 + 255)/256, 256, 0, s2>>>(ew2, we2_h, we2_l, (long)EE*CC*HID/4);
    cudaEventRecord(evJoinMoE, s2);

    // main: qkv weight conv + pipeline
    conv_kernel<<<(3*CC*CC/4 + 255)/256, 256>>>(qkv_w, wqkv_h, wqkv_l, (long)3*CC*CC/4);

    pcfg.gridDim = dim3(NTOK, 1, 1);
    pcfg.blockDim = dim3(256, 1, 1);
    pcfg.dynamicSmemBytes = 0;
    cudaLaunchKernelEx(&pcfg, mix_rms_kernel, x, x0, lambdas);

    cudaStreamWaitEvent(0, evRot, 0);   // rot tables ready before qkv epilogue

    gcfg.gridDim = dim3(CC/256, NTOK/128, 3);
    cudaLaunchKernelEx(&gcfg, gemm_bf<5,false,false>,
        (const bf16*)abf_h, (const bf16*)abf_l, 0L,
        (const bf16*)wqkv_h, (const bf16*)wqkv_l, (long)CC*CC,
        tmQh, tmQl,
        (float*)nullptr, (bf16*)nullptr, (bf16*)nullptr, 0L,
        (const float*)nullptr, 0, (const float*)nullptr,
        (const int*)nullptr, (const int*)nullptr, (const float*)nullptr, (int)CC, (int)CC);

    pcfg.gridDim = dim3(TT/128, 2*HH, 1);
    pcfg.blockDim = dim3(256, 1, 1);
    pcfg.dynamicSmemBytes = SMEM_ATT;
    cudaLaunchKernelEx(&pcfg, attn_tc);

    cudaStreamWaitEvent(0, evJoinCp, 0);
    gcfg.gridDim = dim3(CC/256, NTOK/128, 1);
    cudaLaunchKernelEx(&gcfg, gemm_bf<2,false,false>,
        (const bf16*)obf_h, (const bf16*)obf_l, 0L,
        (const bf16*)wcp_h, (const bf16*)wcp_l, 0L,
        tmCh, tmCl,
        out, (bf16*)nullptr, (bf16*)nullptr, 0L,
        c_proj_b, 0, (const float*)p_xmix,
        (const int*)nullptr, (const int*)nullptr, (const float*)nullptr, (int)CC, (int)CC);

    pcfg.gridDim = dim3(NTOK, 1, 1);
    pcfg.blockDim = dim3(256, 1, 1);
    pcfg.dynamicSmemBytes = 0;
    cudaLaunchKernelEx(&pcfg, rms2_kernel, (const float*)out);

    cudaLaunchKernelEx(&pcfg, router_kernel, router_w, router_b, noise_w, noise_b, noise);

    pcfg.gridDim = dim3(1, 1, 1);
    cudaLaunchKernelEx(&pcfg, build_idx_kernel);

    cudaStreamWaitEvent(0, evJoinMoE, 0);

    gcfg.gridDim = dim3(HID/256, CAPX/128, EE);
    cudaLaunchKernelEx(&gcfg, gemm_bf<3,true,true>,
        (const bf16*)hbf_h, (const bf16*)hbf_l, 0L,
        (const bf16*)we1_h, (const bf16*)we1_l, (long)HID*CC,
        tmE1h, tmE1l,
        (float*)nullptr, h1_h, h1_l, (long)CAPX*HID,
        eb1, (int)HID, (const float*)nullptr,
        (const int*)p_idx, (const int*)p_cnt, (const float*)nullptr, (int)HID, (int)CC);

    gcfg.gridDim = dim3(CC/256, CAPX/128, EE);
    cudaLaunchKernelEx(&gcfg, gemm_bf<4,false,true>,
        (const bf16*)h1_h, (const bf16*)h1_l, (long)CAPX*HID,
        (const bf16*)we2_h, (const bf16*)we2_l, (long)CC*HID,
        tmE2h, tmE2l,
        out, (bf16*)nullptr, (bf16*)nullptr, 0L,
        eb2, (int)CC, (const float*)nullptr,
        (const int*)p_idx, (const int*)p_cnt, (const float*)p_g0, (int)CC, (int)HID);

    cudaEventDestroy(evFork);
    cudaEventDestroy(evRot);
    cudaEventDestroy(evJoinCp);
    cudaEventDestroy(evJoinMoE);
    cudaStreamDestroy(s2);
}

// round 16
// speedup vs baseline: 1.0063x; 1.0063x over previous
#include <cuda_runtime.h>
#include <cuda.h>
#include <cuda_bf16.h>
#include <math.h>
#include <stdint.h>

#define NTOK 4096
#define TT   2048
#define CC   1024
#define HH   16
#define HD   64
#define EE   8
#define CAPX 1024
#define HID  4096

#if defined(__CUDA_ARCH__)
# if (__CUDA_ARCH__ >= 1000) && (defined(__CUDA_ARCH_FEAT_SM103_ALL) || defined(__CUDA_ARCH_FEAT_SM100_ALL) || defined(__CUDA_ARCH_SPECIFIC__) || defined(__CUDA_ARCH_FAMILY_SPECIFIC__))
#  define USE_TC 1
# else
#  define USE_TC 0
# endif
#else
# define USE_TC 0
#endif

typedef __nv_bfloat16 bf16;
typedef __nv_bfloat162 bf162;

// PDL: wait for upstream grid completion + memory flush before touching data.
__device__ __forceinline__ void pdl_sync() {
#if defined(__CUDA_ARCH__) && (__CUDA_ARCH__ >= 900)
    cudaGridDependencySynchronize();
#endif
}

// ---------------- scratch ----------------
__device__ float g_xmix[(size_t)NTOK*CC];
__device__ float g_h   [(size_t)NTOK*CC];
__device__ float g_g0  [NTOK];
__device__ int   g_eid [NTOK];
__device__ int   g_idx [EE*CAPX];
__device__ int   g_cnt [EE];
__device__ float g_rotc[TT*16];
__device__ float g_rots[TT*16];
__device__ bf16 g_abf [2][(size_t)NTOK*CC];
__device__ bf16 g_obf [2][(size_t)NTOK*CC];
__device__ bf16 g_hbf [2][(size_t)NTOK*CC];
__device__ bf16 g_qbf [2][(size_t)NTOK*CC];      // [bh][t][d]
__device__ bf16 g_kbf [2][(size_t)NTOK*CC];      // [bh][t][d]
__device__ bf16 g_vT  [2][(size_t)NTOK*CC];      // [bh][d][t]
__device__ __align__(256) bf16 g_h1bf[2][(size_t)EE*CAPX*HID];
__device__ __align__(256) bf16 g_wqkv[2][(size_t)3*CC*CC];
__device__ __align__(256) bf16 g_wcp [2][(size_t)CC*CC];
__device__ __align__(256) bf16 g_we1 [2][(size_t)EE*HID*CC];
__device__ __align__(256) bf16 g_we2 [2][(size_t)EE*CC*HID];

__constant__ float c_rotinv[16] = {
    1.0f, 0.6299605249474366f, 0.39685026299204984f, 0.25f,
    0.15749013123685915f, 0.09921256574801246f, 0.0625f, 0.03937253280921479f,
    0.024803141437003115f, 0.015625f, 0.009843133202303697f, 0.0062007853592507785f,
    0.00390625f, 0.0024607833005759242f, 0.0015501963398126947f, 0.0009765625f
};

// ---------------- helpers ----------------
__device__ __forceinline__ uint32_t smem_u32(const void* p) {
    uint32_t a;
    asm("{ .reg .u64 t; cvta.to.shared.u64 t, %1; cvt.u32.u64 %0, t; }" : "=r"(a) : "l"(p));
    return a;
}
__device__ __forceinline__ uint32_t sw128(uint32_t off) { return off ^ ((off >> 3) & 0x70); }

__device__ __forceinline__ void cpa16(uint32_t d, const void* s) {
    asm volatile("cp.async.cg.shared.global [%0], [%1], 16;" :: "r"(d), "l"(s) : "memory");
}
#define CPA_COMMIT() asm volatile("cp.async.commit_group;" ::: "memory")
#define CPA_WAIT(n)  asm volatile("cp.async.wait_group %0;" :: "n"(n) : "memory")

__device__ __forceinline__ void split4(float4 v, uint2& hv, uint2& lv) {
    bf16 h0 = __float2bfloat16_rn(v.x), h1 = __float2bfloat16_rn(v.y);
    bf16 h2 = __float2bfloat16_rn(v.z), h3 = __float2bfloat16_rn(v.w);
    bf162 hp0; hp0.x = h0; hp0.y = h1;
    bf162 hp1; hp1.x = h2; hp1.y = h3;
    bf162 lp0 = __floats2bfloat162_rn(v.x - __bfloat162float(h0), v.y - __bfloat162float(h1));
    bf162 lp1 = __floats2bfloat162_rn(v.z - __bfloat162float(h2), v.w - __bfloat162float(h3));
    hv.x = *(uint32_t*)&hp0; hv.y = *(uint32_t*)&hp1;
    lv.x = *(uint32_t*)&lp0; lv.y = *(uint32_t*)&lp1;
}

#if USE_TC
__device__ __forceinline__ uint32_t elect_one() {
    uint32_t p;
    asm volatile("{\n\t.reg .pred p;\n\telect.sync _|p, 0xFFFFFFFF;\n\tselp.b32 %0, 1, 0, p;\n\t}" : "=r"(p));
    return p;
}
__device__ __forceinline__ uint32_t ctarank() {
    uint32_t r;
    asm("mov.u32 %0, %%cluster_ctarank;" : "=r"(r));
    return r;
}
#define CLUSTER_SYNC() do { \
    asm volatile("barrier.cluster.arrive.aligned;" ::: "memory"); \
    asm volatile("barrier.cluster.wait.aligned;" ::: "memory"); \
} while (0)
#define MBAR_INIT(addr, cnt) \
    asm volatile("mbarrier.init.shared.b64 [%0], %1;" :: "r"(addr), "r"(cnt) : "memory")
#define MBAR_EXPECT_TX(addr, bytes) \
    asm volatile("mbarrier.arrive.expect_tx.shared.b64 _, [%0], %1;" :: "r"(addr), "r"(bytes) : "memory")
__device__ __forceinline__ void mbar_wait(uint32_t addr, int phase) {
    uint32_t done = 0;
    while (!done) {
        asm volatile("{\n\t.reg .pred p;\n\t"
            "mbarrier.try_wait.parity.acquire.cta.shared::cta.b64 p, [%1], %2, 0x989680;\n\t"
            "selp.b32 %0, 1, 0, p;\n\t}" : "=r"(done) : "r"(addr), "r"(phase) : "memory");
    }
}
#define TMA_MC_3D(smem, map, x, y, zc, mbar, mask) \
    asm volatile("cp.async.bulk.tensor.3d.shared::cluster.global.tile.mbarrier::complete_tx::bytes.multicast::cluster " \
        "[%0], [%1, {%2, %3, %4}], [%5], %6;" \
        :: "r"(smem), "l"(map), "r"(x), "r"(y), "r"(zc), "r"(mbar), "h"((uint16_t)(mask)) : "memory")
#define TC_ALLOC(addr, n) \
    asm volatile("tcgen05.alloc.cta_group::1.sync.aligned.shared::cta.b32 [%0], %1;" :: "r"(addr), "r"(n) : "memory")
#define TC_DEALLOC(tm, n) \
    asm volatile("tcgen05.dealloc.cta_group::1.sync.aligned.b32 %0, %1;" :: "r"(tm), "r"(n))
#define TC_RELINQ() \
    asm volatile("tcgen05.relinquish_alloc_permit.cta_group::1.sync.aligned;")
#define TC_COMMIT(mbar) \
    asm volatile("tcgen05.commit.cta_group::1.mbarrier::arrive::one.shared::cluster.b64 [%0];" :: "r"(mbar) : "memory")
#define TC_COMMIT_MC(mbar, mask) \
    asm volatile("tcgen05.commit.cta_group::1.mbarrier::arrive::one.shared::cluster.multicast::cluster.b64 [%0], %1;" \
        :: "r"(mbar), "h"((uint16_t)(mask)) : "memory")
#define TC_FENCE_AFTER()  asm volatile("tcgen05.fence::after_thread_sync;" ::: "memory")
#define TC_FENCE_BEFORE() asm volatile("tcgen05.fence::before_thread_sync;" ::: "memory")
#define TC_WAIT_LD()      asm volatile("tcgen05.wait::ld.sync.aligned;" ::: "memory")
#define TC_WAIT_ST()      asm volatile("tcgen05.wait::st.sync.aligned;" ::: "memory")

#define TC_LD_X32(r, a) \
    asm volatile("tcgen05.ld.sync.aligned.32x32b.x32.b32 " \
        "{%0,%1,%2,%3,%4,%5,%6,%7,%8,%9,%10,%11,%12,%13,%14,%15," \
        "%16,%17,%18,%19,%20,%21,%22,%23,%24,%25,%26,%27,%28,%29,%30,%31}, [%32];" \
        : "=r"((r)[0]),"=r"((r)[1]),"=r"((r)[2]),"=r"((r)[3]),"=r"((r)[4]),"=r"((r)[5]),"=r"((r)[6]),"=r"((r)[7]), \
          "=r"((r)[8]),"=r"((r)[9]),"=r"((r)[10]),"=r"((r)[11]),"=r"((r)[12]),"=r"((r)[13]),"=r"((r)[14]),"=r"((r)[15]), \
          "=r"((r)[16]),"=r"((r)[17]),"=r"((r)[18]),"=r"((r)[19]),"=r"((r)[20]),"=r"((r)[21]),"=r"((r)[22]),"=r"((r)[23]), \
          "=r"((r)[24]),"=r"((r)[25]),"=r"((r)[26]),"=r"((r)[27]),"=r"((r)[28]),"=r"((r)[29]),"=r"((r)[30]),"=r"((r)[31]) \
        : "r"(a))

#define TC_ST_X32(a, r) \
    asm volatile("tcgen05.st.sync.aligned.32x32b.x32.b32 [%0], " \
        "{%1,%2,%3,%4,%5,%6,%7,%8,%9,%10,%11,%12,%13,%14,%15,%16," \
        "%17,%18,%19,%20,%21,%22,%23,%24,%25,%26,%27,%28,%29,%30,%31,%32};" \
        :: "r"(a), \
           "r"((r)[0]),"r"((r)[1]),"r"((r)[2]),"r"((r)[3]),"r"((r)[4]),"r"((r)[5]),"r"((r)[6]),"r"((r)[7]), \
           "r"((r)[8]),"r"((r)[9]),"r"((r)[10]),"r"((r)[11]),"r"((r)[12]),"r"((r)[13]),"r"((r)[14]),"r"((r)[15]), \
           "r"((r)[16]),"r"((r)[17]),"r"((r)[18]),"r"((r)[19]),"r"((r)[20]),"r"((r)[21]),"r"((r)[22]),"r"((r)[23]), \
           "r"((r)[24]),"r"((r)[25]),"r"((r)[26]),"r"((r)[27]),"r"((r)[28]),"r"((r)[29]),"r"((r)[30]),"r"((r)[31]) \
        : "memory")

__device__ __forceinline__ void mma_ss_bf16(uint32_t d, uint64_t ad, uint64_t bd,
                                            uint32_t idesc, uint32_t en) {
    asm volatile("{\n\t.reg .pred p;\n\tsetp.ne.u32 p, %4, 0;\n\t"
        "tcgen05.mma.cta_group::1.kind::f16 [%0], %1, %2, %3, {%5,%5,%5,%5}, p;\n\t}"
        :: "r"(d), "l"(ad), "l"(bd), "r"(idesc), "r"(en), "r"(0u) : "memory");
}
__device__ __forceinline__ void mma_ts_bf16(uint32_t d, uint32_t a, uint64_t bd,
                                            uint32_t idesc, uint32_t en) {
    asm volatile("{\n\t.reg .pred p;\n\tsetp.ne.u32 p, %4, 0;\n\t"
        "tcgen05.mma.cta_group::1.kind::f16 [%0], [%1], %2, %3, {%5,%5,%5,%5}, p;\n\t}"
        :: "r"(d), "r"(a), "l"(bd), "r"(idesc), "r"(en), "r"(0u) : "memory");
}
__device__ __forceinline__ uint64_t make_desc(uint32_t base) {
    const uint64_t B = (uint64_t(2) << 61) | (uint64_t(1) << 46) | (uint64_t(64) << 32) | (uint64_t(1) << 16);
    return B | ((uint64_t)(base >> 4) & 0x3FFF);
}
#endif // USE_TC

// ---------------- rotary tables ----------------
__global__ void rot_tab_kernel() {
    int idx = blockIdx.x * 256 + threadIdx.x;
    if (idx >= TT * 16) return;
    int t = idx >> 4, j = idx & 15;
    float th = (float)t * c_rotinv[j];
    g_rotc[idx] = cosf(th);
    g_rots[idx] = sinf(th);
}

// ---------------- fp32 -> hi/lo bf16 ----------------
__global__ void conv_kernel(const float* __restrict__ src, bf16* __restrict__ hi,
                            bf16* __restrict__ lo, long n4) {
    long i = (long)blockIdx.x * blockDim.x + threadIdx.x;
    if (i >= n4) return;
    float4 v = ((const float4*)src)[i];
    uint2 hv, lv; split4(v, hv, lv);
    ((uint2*)hi)[i] = hv; ((uint2*)lo)[i] = lv;
}

// ======= bf16 GEMM: 128x256 tile, 3-term split, cluster-2 B TMA-multicast =======
// EPI: 1=+bias 2=+bias+resid 3=sq(relu(+bias)) 4=scatter 5=fused qk-rot / V-transpose
#define A_PL 16384
#define B_PL 32768
#define BUF_BYTES 98304
#define SMEM_TOTAL_TC (1024 + 2*BUF_BYTES)

template<int EPI, bool GATHER, bool SKIP>
__global__ __launch_bounds__(256)
void gemm_bf(const bf16* __restrict__ Ahi, const bf16* __restrict__ Alo, long aStride,
             const bf16* __restrict__ Bhi, const bf16* __restrict__ Blo, long bStride,
             const __grid_constant__ CUtensorMap tmBh,
             const __grid_constant__ CUtensorMap tmBl,
             float* __restrict__ Cf, bf16* __restrict__ Chi, bf16* __restrict__ Clo, long cStride,
             const float* __restrict__ bias, int biasStride,
             const float* __restrict__ resid,
             const int* __restrict__ rowIdx,
             const int* __restrict__ counts,
             const float* __restrict__ g0,
             int Nt, int Kd) {
    extern __shared__ char smem[];
    pdl_sync();   // upstream data (A, rowIdx/counts, resid) fully visible
    const int z = blockIdx.z;
    const int m0 = blockIdx.y * 128, n0 = blockIdx.x * 256;
    int cnt = 0;
    if (SKIP) {
        cnt = counts[z];
        int pairBase = (int)(blockIdx.y & ~1u) * 128;   // pair-level skip (cluster lockstep)
        if (pairBase >= cnt) return;
    }
    bool active = !SKIP || (m0 < cnt);
    int tid = threadIdx.x, wid = tid >> 5, lane = tid & 31;

    const uint32_t OFF_MB = 8, OFF_RID = 64, OFF_TILE = 1024;
    int* s_rid = (int*)(smem + OFF_RID);
    if (tid < 128) {
        int r;
        if (GATHER) r = min(rowIdx[z * CAPX + m0 + tid], NTOK - 1);
        else        r = m0 + tid;
        s_rid[tid] = r;
    }
    const bf16* Ahz = Ahi + (size_t)z * aStride;
    const bf16* Alz = Alo + (size_t)z * aStride;

#if USE_TC
    uint32_t sbase = smem_u32(smem);
    uint32_t rank = ctarank();
    const uint32_t MB0 = sbase + OFF_MB,      MB1 = sbase + OFF_MB + 8;
    const uint32_t BB0 = sbase + OFF_MB + 16, BB1 = sbase + OFF_MB + 24;
    if (tid == 0) {
        MBAR_INIT(MB0, 2); MBAR_INIT(MB1, 2);
        MBAR_INIT(BB0, 1); MBAR_INIT(BB1, 1);
    }
    if (wid == 0) { TC_ALLOC(sbase + 0, 256u); }
    __syncthreads();
    CLUSTER_SYNC();
    uint32_t tmem = *(uint32_t*)(smem + 0);

    const uint32_t idesc = (1u << 4) | (1u << 7) | (1u << 10) | (32u << 17) | (8u << 24); // N=256

    int nchunks = Kd >> 6;

    auto issue_A = [&](int c, uint32_t tb) {
        int k0 = c * 64;
        #pragma unroll
        for (int i = 0; i < 4; i++) {
            int f = tid + i * 256;
            int row = f >> 3, c8 = f & 7;
            uint32_t so = sw128((uint32_t)(row * 128 + c8 * 16));
            size_t aoff = (size_t)s_rid[row] * Kd + k0 + c8 * 8;
            cpa16(tb + so,        Ahz + aoff);
            cpa16(tb + A_PL + so, Alz + aoff);
        }
        CPA_COMMIT();
    };
    auto issue_B = [&](int c, int buf) {
        if (tid != 0) return;
        uint32_t tb = sbase + OFF_TILE + (uint32_t)buf * BUF_BYTES;
        uint32_t bb = buf ? BB1 : BB0;
        MBAR_EXPECT_TX(bb, 65536u);
        uint32_t soff = rank ? 16384u : 0u;
        int k0 = c * 64;
        int ycoord = n0 + (int)rank * 128;
        TMA_MC_3D(tb + 2 * A_PL + soff,        &tmBh, k0, ycoord, z, bb, 3);
        TMA_MC_3D(tb + 2 * A_PL + B_PL + soff, &tmBl, k0, ycoord, z, bb, 3);
    };

    issue_A(0, sbase + OFF_TILE);
    issue_B(0, 0);

    int ph0 = 0, ph1 = 0, pb0 = 0, pb1 = 0;

    for (int c = 0; c < nchunks; c++) {
        int buf = c & 1;
        uint32_t tb = sbase + OFF_TILE + buf * BUF_BYTES;
        if (c + 1 < nchunks) {
            if (c >= 1) {
                if ((buf ^ 1) == 0) { mbar_wait(MB0, ph0); ph0 ^= 1; }
                else                { mbar_wait(MB1, ph1); ph1 ^= 1; }
            }
            issue_A(c + 1, sbase + OFF_TILE + (buf ^ 1) * BUF_BYTES);
            issue_B(c + 1, buf ^ 1);
            CPA_WAIT(1);
        } else {
            CPA_WAIT(0);
        }
        if (buf == 0) { mbar_wait(BB0, pb0); pb0 ^= 1; }
        else          { mbar_wait(BB1, pb1); pb1 ^= 1; }
        asm volatile("fence.proxy.async.shared::cta;" ::: "memory");
        __syncthreads();
        if (wid == 0) {
            if (elect_one()) {
                uint64_t ah = make_desc(tb);
                uint64_t al = make_desc(tb + A_PL);
                uint64_t bh = make_desc(tb + 2 * A_PL);
                uint64_t bl = make_desc(tb + 2 * A_PL + B_PL);
                #pragma unroll
                for (int ks = 0; ks < 4; ks++) {
                    uint64_t o = ks * 2;
                    mma_ss_bf16(tmem, ah + o, bh + o, idesc, (c > 0 || ks > 0) ? 1u : 0u);
                    mma_ss_bf16(tmem, ah + o, bl + o, idesc, 1u);
                    mma_ss_bf16(tmem, al + o, bh + o, idesc, 1u);
                }
                TC_COMMIT_MC(buf == 0 ? MB0 : MB1, 3);
            }
        }
    }
    mbar_wait(MB0, ph0);
    mbar_wait(MB1, ph1);
    TC_FENCE_AFTER();
    CLUSTER_SYNC();

    int colbase = (wid >> 2) * 128;
    int row = (wid & 3) * 32 + lane;
    int gm = m0 + row;

    if (EPI == 5) {
        if (z < 2) {
            int t = gm & (TT - 1), bb = gm >> 11;
            bf16* hip = z ? g_kbf[0] : g_qbf[0];
            bf16* lop = z ? g_kbf[1] : g_qbf[1];
            const float* ctab = g_rotc + t * 16;
            const float* stab = g_rots + t * 16;
            float cv[16], sv[16];
            #pragma unroll
            for (int d = 0; d < 16; d += 4) {
                float4 c4 = *(const float4*)(ctab + d);
                float4 s4 = *(const float4*)(stab + d);
                cv[d] = c4.x; cv[d+1] = c4.y; cv[d+2] = c4.z; cv[d+3] = c4.w;
                sv[d] = s4.x; sv[d+1] = s4.y; sv[d+2] = s4.z; sv[d+3] = s4.w;
            }
            #pragma unroll
            for (int g2 = 0; g2 < 2; g2++) {
                int co = colbase + g2 * 64;
                uint32_t dr[64];
                TC_LD_X32(dr,      tmem + co);
                TC_LD_X32(dr + 32, tmem + co + 32);
                TC_WAIT_LD();
                float v[64]; float ss = 0.f;
                #pragma unroll
                for (int j = 0; j < 64; j++) { v[j] = __uint_as_float(dr[j]); ss += v[j] * v[j]; }
                float sc = rsqrtf(ss * (1.0f / HD) + 1e-6f);
                float o[64];
                #pragma unroll
                for (int d = 0; d < 16; d++) {
                    float x1 = v[d] * sc, x2 = v[d + 32] * sc;
                    o[d]      =  x1 * cv[d] + x2 * sv[d];
                    o[d + 32] = -x1 * sv[d] + x2 * cv[d];
                }
                #pragma unroll
                for (int d = 16; d < 32; d++) {
                    o[d]      = v[d] * sc;
                    o[d + 32] = v[d + 32] * sc;
                }
                int hh = (n0 + co) >> 6;
                size_t basep = ((size_t)(bb * HH + hh) * TT + t) * HD;
                #pragma unroll
                for (int j = 0; j < 64; j += 4) {
                    float4 f4; f4.x = o[j]; f4.y = o[j+1]; f4.z = o[j+2]; f4.w = o[j+3];
                    uint2 hv, lv; split4(f4, hv, lv);
                    *(uint2*)(hip + basep + j) = hv;
                    *(uint2*)(lop + basep + j) = lv;
                }
            }
        } else {
            const int TP = 136;
            bf16* sh = (bf16*)(smem + OFF_TILE);
            __syncthreads();
            #pragma unroll
            for (int g2 = 0; g2 < 2; g2++) {
                int co = colbase + g2 * 64;
                uint32_t dr[64];
                TC_LD_X32(dr,      tmem + co);
                TC_LD_X32(dr + 32, tmem + co + 32);
                TC_WAIT_LD();
                #pragma unroll
                for (int j = 0; j < 64; j++) {
                    float vv = __uint_as_float(dr[j]);
                    bf16 hv = __float2bfloat16_rn(vv);
                    bf16 lv = __float2bfloat16_rn(vv - __bfloat162float(hv));
                    sh[(size_t)(co + j) * TP + row]       = hv;
                    sh[(size_t)(256 + co + j) * TP + row] = lv;
                }
            }
            __syncthreads();
            int bb2 = m0 >> 11, t0 = m0 & (TT - 1);
            int col = n0 + tid;
            int hh = col >> 6, dd = col & 63;
            size_t dst = ((size_t)((bb2 * HH + hh) * HD + dd)) * TT + t0;
            const bf16* s0 = sh + (size_t)tid * TP;
            const bf16* s1 = sh + (size_t)(256 + tid) * TP;
            #pragma unroll
            for (int q = 0; q < 128; q += 8) {
                *(uint4*)(g_vT[0] + dst + q) = *(const uint4*)(s0 + q);
                *(uint4*)(g_vT[1] + dst + q) = *(const uint4*)(s1 + q);
            }
        }
    } else {
        int token = 0; float gg = 0.f; bool valid4 = active;
        if (EPI == 4) {
            valid4 = active && (gm < cnt);
            if (valid4) { token = rowIdx[z * CAPX + gm]; gg = g0[token]; }
        }
        #pragma unroll
        for (int g2 = 0; g2 < 2; g2++) {
            int co = colbase + g2 * 64;
            uint32_t dr[64];
            TC_LD_X32(dr,      tmem + co);
            TC_LD_X32(dr + 32, tmem + co + 32);
            TC_WAIT_LD();

            const float* bp = (EPI >= 1) ? (bias + (size_t)z * biasStride + n0 + co) : nullptr;
            if (EPI == 3) {
                if (active) {
                    bf16* chp = Chi + (size_t)z * cStride + (size_t)gm * Nt + n0 + co;
                    bf16* clp = Clo + (size_t)z * cStride + (size_t)gm * Nt + n0 + co;
                    #pragma unroll
                    for (int j = 0; j < 64; j += 4) {
                        float4 v;
                        float t0 = __uint_as_float(dr[j+0]) + bp[j+0];
                        float t1 = __uint_as_float(dr[j+1]) + bp[j+1];
                        float t2 = __uint_as_float(dr[j+2]) + bp[j+2];
                        float t3 = __uint_as_float(dr[j+3]) + bp[j+3];
                        v.x = t0 > 0.f ? t0*t0 : 0.f; v.y = t1 > 0.f ? t1*t1 : 0.f;
                        v.z = t2 > 0.f ? t2*t2 : 0.f; v.w = t3 > 0.f ? t3*t3 : 0.f;
                        uint2 hv, lv; split4(v, hv, lv);
                        *(uint2*)(chp + j) = hv; *(uint2*)(clp + j) = lv;
                    }
                }
            } else if (EPI == 4) {
                if (valid4) {
                    float* op = Cf + (size_t)token * Nt + n0 + co;
                    #pragma unroll
                    for (int j = 0; j < 64; j += 4) {
                        float4 o = *(float4*)(op + j);
                        o.x += gg * (__uint_as_float(dr[j+0]) + bp[j+0]);
                        o.y += gg * (__uint_as_float(dr[j+1]) + bp[j+1]);
                        o.z += gg * (__uint_as_float(dr[j+2]) + bp[j+2]);
                        o.w += gg * (__uint_as_float(dr[j+3]) + bp[j+3]);
                        *(float4*)(op + j) = o;
                    }
                }
            } else {
                const float* rp = (EPI == 2) ? (resid + (size_t)gm * Nt + n0 + co) : nullptr;
                float* cp = Cf + (size_t)z * cStride + (size_t)gm * Nt + n0 + co;
                #pragma unroll
                for (int j = 0; j < 64; j += 4) {
                    float vv[4];
                    #pragma unroll
                    for (int q = 0; q < 4; q++) {
                        float t = __uint_as_float(dr[j + q]);
                        if (EPI == 1)      t += bp[j + q];
                        else if (EPI == 2) t += bp[j + q] + rp[j + q];
                        vv[q] = t;
                    }
                    float4 v4; v4.x = vv[0]; v4.y = vv[1]; v4.z = vv[2]; v4.w = vv[3];
                    *(float4*)(cp + j) = v4;
                }
            }
        }
    }

    TC_FENCE_BEFORE();
    __syncthreads();
    if (wid == 0) { TC_RELINQ(); TC_DEALLOC(tmem, 256u); }

#else  // SIMT fallback (non-arch-specific pass; never selected on GB300)
    const bf16* Bhz = Bhi + (size_t)z * bStride;
    const bf16* Blz = Blo + (size_t)z * bStride;
    float* As = (float*)(smem + OFF_TILE);
    float* Bs = (float*)(smem + OFF_TILE + 16 * 128 * 4);
    float* Stg = (float*)(smem + OFF_TILE + 32 * 128 * 4);
    __syncthreads();
    int tm = (tid >> 4) * 8, tn = (tid & 15) * 8;
    for (int nsub = 0; nsub < 2; nsub++) {
        int n0s = n0 + nsub * 128;
        float acc[8][8];
        #pragma unroll
        for (int i = 0; i < 8; i++)
            #pragma unroll
            for (int j = 0; j < 8; j++) acc[i][j] = 0.f;
        for (int k0 = 0; k0 < Kd; k0 += 16) {
            #pragma unroll
            for (int i = 0; i < 2; i++) {
                int f = tid + i * 256;
                int rw_ = f >> 2, c4 = (f & 3) * 4;
                #pragma unroll
                for (int q = 0; q < 4; q++) {
                    size_t ao = (size_t)s_rid[rw_] * Kd + k0 + c4 + q;
                    size_t bo = (size_t)(n0s + rw_) * Kd + k0 + c4 + q;
                    As[(c4+q)*128 + rw_] = __bfloat162float(Ahz[ao]) + __bfloat162float(Alz[ao]);
                    Bs[(c4+q)*128 + rw_] = __bfloat162float(Bhz[bo]) + __bfloat162float(Blz[bo]);
                }
            }
            __syncthreads();
            #pragma unroll
            for (int kk = 0; kk < 16; kk++) {
                float a_[8], b_[8];
                #pragma unroll
                for (int q = 0; q < 8; q++) { a_[q] = As[kk*128 + tm + q]; b_[q] = Bs[kk*128 + tn + q]; }
                #pragma unroll
                for (int i = 0; i < 8; i++)
                    #pragma unroll
                    for (int j = 0; j < 8; j++)
                        acc[i][j] += a_[i] * b_[j];
            }
            __syncthreads();
        }
        if (EPI == 5) {
            #pragma unroll
            for (int i = 0; i < 8; i++)
                #pragma unroll
                for (int j = 0; j < 8; j++)
                    Stg[(tm + i) * 132 + tn + j] = acc[i][j];
            __syncthreads();
            int r = tid >> 1, hseg = tid & 1;
            int gmr = m0 + r;
            int t = gmr & (TT - 1), bb = gmr >> 11;
            float v[64];
            #pragma unroll
            for (int j = 0; j < 64; j++) v[j] = Stg[r * 132 + hseg * 64 + j];
            int col0 = n0s + hseg * 64;
            int hh = col0 >> 6;
            if (z < 2) {
                float ss = 0.f;
                #pragma unroll
                for (int j = 0; j < 64; j++) ss += v[j] * v[j];
                float sc = rsqrtf(ss * (1.0f / HD) + 1e-6f);
                bf16* hip = z ? g_kbf[0] : g_qbf[0];
                bf16* lop = z ? g_kbf[1] : g_qbf[1];
                size_t basep = ((size_t)(bb * HH + hh) * TT + t) * HD;
                #pragma unroll
                for (int d = 0; d < 32; d++) {
                    float x1 = v[d] * sc, x2 = v[d + 32] * sc;
                    float cth = (d < 16) ? g_rotc[t * 16 + d] : 1.f;
                    float sth = (d < 16) ? g_rots[t * 16 + d] : 0.f;
                    float y1 = x1 * cth + x2 * sth;
                    float y2 = -x1 * sth + x2 * cth;
                    bf16 h1 = __float2bfloat16_rn(y1), h2 = __float2bfloat16_rn(y2);
                    hip[basep + d] = h1; hip[basep + d + 32] = h2;
                    lop[basep + d] = __float2bfloat16_rn(y1 - __bfloat162float(h1));
                    lop[basep + d + 32] = __float2bfloat16_rn(y2 - __bfloat162float(h2));
                }
            } else {
                #pragma unroll
                for (int d = 0; d < 64; d++) {
                    float vv = v[d];
                    bf16 hv = __float2bfloat16_rn(vv);
                    size_t dst = ((size_t)((bb * HH + hh) * HD + d)) * TT + t;
                    g_vT[0][dst] = hv;
                    g_vT[1][dst] = __float2bfloat16_rn(vv - __bfloat162float(hv));
                }
            }
            __syncthreads();
        } else {
            #pragma unroll
            for (int i = 0; i < 8; i++) {
                int gmr = m0 + tm + i;
                bool act = !SKIP || (m0 < cnt);
                #pragma unroll
                for (int j = 0; j < 8; j++) {
                    float t = acc[i][j];
                    int col = n0s + tn + j;
                    if (EPI >= 1 && EPI <= 4) t += bias[(size_t)z * biasStride + col];
                    if (EPI == 2) t += resid[(size_t)gmr * Nt + col];
                    if (EPI == 3) {
                        if (act) {
                            t = t > 0.f ? t * t : 0.f;
                            bf16 hv = __float2bfloat16_rn(t);
                            Chi[(size_t)z * cStride + (size_t)gmr * Nt + col] = hv;
                            Clo[(size_t)z * cStride + (size_t)gmr * Nt + col] = __float2bfloat16_rn(t - __bfloat162float(hv));
                        }
                    } else if (EPI == 4) {
                        if (act && gmr < cnt) {
                            int token = rowIdx[z * CAPX + gmr];
                            atomicAdd(&Cf[(size_t)token * Nt + col], g0[token] * t);
                        }
                    } else {
                        Cf[(size_t)z * cStride + (size_t)gmr * Nt + col] = t;
                    }
                }
            }
        }
    }
#endif
}

// ---------------- block reduce ----------------
__device__ __forceinline__ float blockReduceSum(float v) {
    __shared__ float sh[32];
    int lane = threadIdx.x & 31, w = threadIdx.x >> 5;
    #pragma unroll
    for (int o = 16; o; o >>= 1) v += __shfl_down_sync(0xffffffffu, v, o);
    if (lane == 0) sh[w] = v;
    __syncthreads();
    int nw = blockDim.x >> 5;
    if (w == 0) {
        v = (lane < nw) ? sh[lane] : 0.f;
        #pragma unroll
        for (int o = 16; o; o >>= 1) v += __shfl_down_sync(0xffffffffu, v, o);
        if (lane == 0) sh[0] = v;
    }
    __syncthreads();
    return sh[0];
}

// ---------------- 1) residual mix + rmsnorm ----------------
__global__ void mix_rms_kernel(const float* __restrict__ x, const float* __restrict__ x0,
                               const float* __restrict__ lambdas) {
    pdl_sync();
    int row = blockIdx.x;
    float l0 = lambdas[0], l1 = lambdas[1];
    size_t off = (size_t)row * CC + threadIdx.x * 4;
    float4 a = *(const float4*)(x + off);
    float4 b = *(const float4*)(x0 + off);
    float4 v;
    v.x = l0*a.x + l1*b.x; v.y = l0*a.y + l1*b.y;
    v.z = l0*a.z + l1*b.z; v.w = l0*a.w + l1*b.w;
    *(float4*)(g_xmix + off) = v;
    float ss = v.x*v.x + v.y*v.y + v.z*v.z + v.w*v.w;
    float tot = blockReduceSum(ss);
    float sc = rsqrtf(tot * (1.0f/CC) + 1e-6f);
    float4 o; o.x = v.x*sc; o.y = v.y*sc; o.z = v.z*sc; o.w = v.w*sc;
    uint2 hv, lv; split4(o, hv, lv);
    *(uint2*)(&g_abf[0][off]) = hv;
    *(uint2*)(&g_abf[1][off]) = lv;
}

// ---------------- 6) rmsnorm of x2 ----------------
__global__ void rms2_kernel(const float* __restrict__ src) {
    pdl_sync();
    int row = blockIdx.x;
    size_t off = (size_t)row * CC + threadIdx.x * 4;
    float4 v = *(const float4*)(src + off);
    float ss = v.x*v.x + v.y*v.y + v.z*v.z + v.w*v.w;
    float tot = blockReduceSum(ss);
    float sc = rsqrtf(tot * (1.0f/CC) + 1e-6f);
    float4 o; o.x = v.x*sc; o.y = v.y*sc; o.z = v.z*sc; o.w = v.w*sc;
    *(float4*)(g_h + off) = o;
    uint2 hv, lv; split4(o, hv, lv);
    *(uint2*)(&g_hbf[0][off]) = hv;
    *(uint2*)(&g_hbf[1][off]) = lv;
}

// ---------------- 4) pipelined tensor-core causal attention ----------------
#define AT_QHI 2048
#define AT_QLO (AT_QHI + 16384)
#define AT_KBUF 34816
#define AT_VBUF (AT_KBUF + 3*32768)
#define SMEM_ATT (AT_VBUF + 2*32768)
#define AT_L2 128

__global__ __launch_bounds__(256) void attn_tc() {
    extern __shared__ char smem[];
    int qtile = gridDim.x - 1 - blockIdx.x;   // LPT
    int bh = blockIdx.y;
    int b = bh >> 4, h = bh & 15;
    int q0 = qtile * 128;
    int tid = threadIdx.x, wid = tid >> 5, lane = tid & 31;
    int half = wid >> 2;
    int row = (wid & 3) * 32 + lane;

    const bf16* qh_g = g_qbf[0] + ((size_t)bh * TT + q0) * HD;
    const bf16* ql_g = g_qbf[1] + ((size_t)bh * TT + q0) * HD;

#if USE_TC
    uint32_t sbase = smem_u32(smem);
    const uint32_t MBS = sbase + 8, MBA = sbase + 16;
    float* l2s = (float*)(smem + AT_L2);
    if (tid == 0) { MBAR_INIT(MBS, 1); MBAR_INIT(MBA, 1); }
    if (wid == 0) { TC_ALLOC(sbase + 0, 512u); }   // independent prologue under PDL
    pdl_sync();                                    // qkv GEMM outputs now visible

    auto load_K = [&](int kt) {
        uint32_t kb = sbase + AT_KBUF + (uint32_t)(kt % 3) * 32768;
        const bf16* kh_g = g_kbf[0] + ((size_t)bh * TT + kt * 128) * HD;
        const bf16* kl_g = g_kbf[1] + ((size_t)bh * TT + kt * 128) * HD;
        #pragma unroll
        for (int i = 0; i < 4; i++) {
            int f = tid + i * 256;
            int r = f >> 3, c8 = f & 7;
            uint32_t so = sw128((uint32_t)(r * 128 + c8 * 16));
            cpa16(kb + so,         kh_g + (size_t)r * HD + c8 * 8);
            cpa16(kb + 16384 + so, kl_g + (size_t)r * HD + c8 * 8);
        }
    };
    auto load_V = [&](int kt) {
        uint32_t vb = sbase + AT_VBUF + (uint32_t)(kt & 1) * 32768;
        const bf16* vh_g = g_vT[0] + (size_t)bh * HD * TT + kt * 128;
        const bf16* vl_g = g_vT[1] + (size_t)bh * HD * TT + kt * 128;
        #pragma unroll
        for (int i = 0; i < 4; i++) {
            int f = tid + i * 256;
            int d = f >> 4, c16 = f & 15;
            uint32_t byte = (uint32_t)((d >> 3) * 1024 + (c16 >> 3) * 8192 + (d & 7) * 128 + (c16 & 7) * 16);
            uint32_t so = sw128(byte);
            cpa16(vb + so,         vh_g + (size_t)d * TT + c16 * 8);
            cpa16(vb + 16384 + so, vl_g + (size_t)d * TT + c16 * 8);
        }
    };

    {
        #pragma unroll
        for (int i = 0; i < 4; i++) {
            int f = tid + i * 256;
            int r = f >> 3, c8 = f & 7;
            uint32_t so = sw128((uint32_t)(r * 128 + c8 * 16));
            cpa16(sbase + AT_QHI + so, qh_g + (size_t)r * HD + c8 * 8);
            cpa16(sbase + AT_QLO + so, ql_g + (size_t)r * HD + c8 * 8);
        }
        load_K(0);
        load_V(0);
        CPA_COMMIT();
        if (qtile >= 1) { load_K(1); CPA_COMMIT(); }
    }
    __syncthreads();
    uint32_t tmem = *(uint32_t*)(smem + 0);
    const uint32_t S0 = 0, O_OFF = 256, P0 = 320;
    const uint32_t IDS = (1u<<4)|(1u<<7)|(1u<<10)|(16u<<17)|(8u<<24);  // N=128
    const uint32_t IDA = (1u<<4)|(1u<<7)|(1u<<10)|( 8u<<17)|(8u<<24);  // N=64

    CPA_WAIT(0);
    asm volatile("fence.proxy.async.shared::cta;" ::: "memory");
    __syncthreads();

    uint64_t qhd = make_desc(sbase + AT_QHI);
    uint64_t qld = make_desc(sbase + AT_QLO);

    auto issue_S = [&](int kt) {
        uint32_t kb = sbase + AT_KBUF + (uint32_t)(kt % 3) * 32768;
        uint64_t kh = make_desc(kb);
        uint64_t kl = make_desc(kb + 16384);
        uint32_t sd = tmem + S0 + (uint32_t)(kt & 1) * 128;
        #pragma unroll
        for (int ks = 0; ks < 4; ks++) {
            uint64_t o = ks * 2;
            mma_ss_bf16(sd, qhd + o, kh + o, IDS, ks > 0 ? 1u : 0u);
            mma_ss_bf16(sd, qhd + o, kl + o, IDS, 1u);
            mma_ss_bf16(sd, qld + o, kh + o, IDS, 1u);
        }
        TC_COMMIT(MBS);
    };

    if (wid == 0 && elect_one()) issue_S(0);

    float l = 0.f;
    int phS = 0, phA = 0;

    for (int kt = 0; kt <= qtile; kt++) {
        int sbuf = kt & 1;
        if (kt + 2 <= qtile) { load_K(kt + 2); CPA_COMMIT(); }
        mbar_wait(MBS, phS); phS ^= 1;
        TC_FENCE_AFTER();
        if (kt + 2 <= qtile) { CPA_WAIT(1); } else { CPA_WAIT(0); }
        asm volatile("fence.proxy.async.shared::cta;" ::: "memory");
        __syncthreads();
        if (kt < qtile && wid == 0) {
            if (elect_one()) { TC_FENCE_AFTER(); issue_S(kt + 1); }
        }

        uint32_t sr[64];
        TC_LD_X32(sr, tmem + S0 + sbuf * 128 + half * 64);
        TC_WAIT_LD();
        TC_LD_X32(sr + 32, tmem + S0 + sbuf * 128 + half * 64 + 32);

        int qg = q0 + row;
        int kbase = kt * 128 + half * 64;
        bool maskTile = (kt == qtile);
        uint32_t pw[32];
        float lacc = 0.f;
        #pragma unroll
        for (int j2 = 0; j2 < 16; j2++) {
            float s0v = __uint_as_float(sr[2*j2])   * 0.125f;
            float s1v = __uint_as_float(sr[2*j2+1]) * 0.125f;
            float p0 = __expf(s0v), p1 = __expf(s1v);
            if (maskTile) {
                if (kbase + 2*j2     > qg) p0 = 0.f;
                if (kbase + 2*j2 + 1 > qg) p1 = 0.f;
            }
            bf162 pb = __floats2bfloat162_rn(p0, p1);
            lacc += __bfloat162float(pb.x) + __bfloat162float(pb.y);
            pw[j2] = *(uint32_t*)&pb;
        }
        TC_WAIT_LD();
        #pragma unroll
        for (int j2 = 16; j2 < 32; j2++) {
            float s0v = __uint_as_float(sr[2*j2])   * 0.125f;
            float s1v = __uint_as_float(sr[2*j2+1]) * 0.125f;
            float p0 = __expf(s0v), p1 = __expf(s1v);
            if (maskTile) {
                if (kbase + 2*j2     > qg) p0 = 0.f;
                if (kbase + 2*j2 + 1 > qg) p1 = 0.f;
            }
            bf162 pb = __floats2bfloat162_rn(p0, p1);
            lacc += __bfloat162float(pb.x) + __bfloat162float(pb.y);
            pw[j2] = *(uint32_t*)&pb;
        }
        l += lacc;

        if (kt > 0) { mbar_wait(MBA, phA); phA ^= 1; }

        if (kt < qtile) { load_V(kt + 1); CPA_COMMIT(); }

        TC_ST_X32(tmem + P0 + sbuf * 64 + half * 32 + ((uint32_t)(wid & 3) << 21), pw);
        TC_WAIT_ST();
        TC_FENCE_BEFORE();
        __syncthreads();

        if (wid == 0 && elect_one()) {
            TC_FENCE_AFTER();
            uint32_t vb = sbase + AT_VBUF + (uint32_t)sbuf * 32768;
            uint64_t vh = make_desc(vb);
            uint64_t vl = make_desc(vb + 16384);
            #pragma unroll
            for (int ks = 0; ks < 8; ks++) {
                uint64_t vo = (uint64_t)((ks & 3) * 2 + (ks >> 2) * 512);
                uint32_t at = tmem + P0 + sbuf * 64 + ks * 8;
                mma_ts_bf16(tmem + O_OFF, at, vh + vo, IDA, (kt > 0 || ks > 0) ? 1u : 0u);
                mma_ts_bf16(tmem + O_OFF, at, vl + vo, IDA, 1u);
            }
            TC_COMMIT(MBA);
        }
    }
    mbar_wait(MBA, phA);
    TC_FENCE_AFTER();

    l2s[half * 128 + row] = l;
    __syncthreads();
    float inv = 1.f / (l2s[row] + l2s[128 + row]);

    uint32_t od[32];
    TC_LD_X32(od, tmem + O_OFF + half * 32);
    TC_WAIT_LD();
    int token = b * TT + q0 + row;
    bf16* ohp = g_obf[0] + (size_t)token * CC + h * HD + half * 32;
    bf16* olp = g_obf[1] + (size_t)token * CC + h * HD + half * 32;
    #pragma unroll
    for (int j = 0; j < 32; j += 4) {
        float4 v;
        v.x = __uint_as_float(od[j+0]) * inv;
        v.y = __uint_as_float(od[j+1]) * inv;
        v.z = __uint_as_float(od[j+2]) * inv;
        v.w = __uint_as_float(od[j+3]) * inv;
        uint2 hv, lv; split4(v, hv, lv);
        *(uint2*)(ohp + j) = hv; *(uint2*)(olp + j) = lv;
    }
    TC_FENCE_BEFORE();
    __syncthreads();
    if (wid == 0) { TC_RELINQ(); TC_DEALLOC(tmem, 512u); }

#else // SIMT fallback attention
    pdl_sync();
    for (int qq = tid; qq < 128; qq += 256) {
        int qg = q0 + qq;
        float q[HD], o[HD];
        #pragma unroll
        for (int d = 0; d < HD; d++) {
            q[d] = (__bfloat162float(qh_g[(size_t)qq*HD+d]) + __bfloat162float(ql_g[(size_t)qq*HD+d])) * 0.125f;
            o[d] = 0.f;
        }
        float l = 0.f;
        for (int k = 0; k <= qg; k++) {
            const bf16* kh_g = g_kbf[0] + ((size_t)bh * TT + k) * HD;
            const bf16* kl_g = g_kbf[1] + ((size_t)bh * TT + k) * HD;
            float s = 0.f;
            #pragma unroll
            for (int d = 0; d < HD; d++)
                s += q[d] * (__bfloat162float(kh_g[d]) + __bfloat162float(kl_g[d]));
            float p = __expf(s);
            l += p;
            #pragma unroll
            for (int d = 0; d < HD; d++) {
                size_t vo = ((size_t)bh * HD + d) * TT + k;
                o[d] += p * (__bfloat162float(g_vT[0][vo]) + __bfloat162float(g_vT[1][vo]));
            }
        }
        float inv = 1.f / l;
        int token = b * TT + qg;
        #pragma unroll
        for (int d = 0; d < HD; d++) {
            float v = o[d] * inv;
            bf16 hv = __float2bfloat16_rn(v);
            g_obf[0][(size_t)token * CC + h * HD + d] = hv;
            g_obf[1][(size_t)token * CC + h * HD + d] = __float2bfloat16_rn(v - __bfloat162float(hv));
        }
    }
#endif
}

// ---------------- 7) router ----------------
__global__ void router_kernel(const float* __restrict__ rw, const float* __restrict__ rb,
                              const float* __restrict__ nw, const float* __restrict__ nb,
                              const float* __restrict__ noise) {
    pdl_sync();
    int n = blockIdx.x;
    int w = threadIdx.x >> 5, lane = threadIdx.x & 31;
    const float* hr = g_h + (size_t)n * CC;
    const float* wr = rw + (size_t)w * CC;
    const float* wn = nw + (size_t)w * CC;
    float s1 = 0.f, s2 = 0.f;
    for (int c = lane * 4; c < CC; c += 128) {
        float4 hv = *(const float4*)(hr + c);
        float4 r4 = *(const float4*)(wr + c);
        float4 n4 = *(const float4*)(wn + c);
        s1 += hv.x*r4.x + hv.y*r4.y + hv.z*r4.z + hv.w*r4.w;
        s2 += hv.x*n4.x + hv.y*n4.y + hv.z*n4.z + hv.w*n4.w;
    }
    #pragma unroll
    for (int o = 16; o; o >>= 1) {
        s1 += __shfl_xor_sync(0xffffffffu, s1, o);
        s2 += __shfl_xor_sync(0xffffffffu, s2, o);
    }
    __shared__ float lg[8], nl[8];
    if (lane == 0) { lg[w] = s1 + rb[w]; nl[w] = s2 + nb[w]; }
    __syncthreads();
    if (threadIdx.x == 0) {
        float nv[8];
        #pragma unroll
        for (int e = 0; e < 8; e++) {
            float xn = nl[e];
            float sp = (xn > 20.f) ? xn : log1pf(expf(xn));
            nv[e] = lg[e] + noise[(size_t)n * EE + e] * sp;
        }
        int i0 = 0; float v0 = nv[0];
        #pragma unroll
        for (int e = 1; e < 8; e++) if (nv[e] > v0) { v0 = nv[e]; i0 = e; }
        float v1 = -1e30f;
        #pragma unroll
        for (int e = 0; e < 8; e++) if (e != i0 && nv[e] > v1) { v1 = nv[e]; }
        float e1 = expf(v1 - v0);
        g_g0[n] = 1.f / (1.f + e1);
        g_eid[n] = i0;
    }
}

// ---------------- 8) per-expert capacity lists ----------------
__global__ void build_idx_kernel() {
    pdl_sync();
    int w = threadIdx.x >> 5, lane = threadIdx.x & 31;
    int count = 0;
    for (int base = 0; base < NTOK; base += 32) {
        int t = base + lane;
        bool p = (g_eid[t] == w);
        unsigned msk = __ballot_sync(0xffffffffu, p);
        int pos = count + __popc(msk & ((1u << lane) - 1u));
        if (p && pos < CAPX) g_idx[w * CAPX + pos] = t;
        count += __popc(msk);
    }
    int c = min(count, CAPX);
    if (lane == 0) g_cnt[w] = c;
    for (int s = c + lane; s < CAPX; s += 32) g_idx[w * CAPX + s] = NTOK;
}

// ---------------- host: tensormap encode via driver entry point ----------------
typedef CUresult (*EncodeFn)(CUtensorMap*, CUtensorMapDataType, cuuint32_t, void*,
    const cuuint64_t*, const cuuint64_t*, const cuuint32_t*, const cuuint32_t*,
    CUtensorMapInterleave, CUtensorMapSwizzle, CUtensorMapL2promotion, CUtensorMapFloatOOBfill);

static EncodeFn get_encode_fn() {
    static EncodeFn fn = nullptr;
    if (!fn) {
        void* p = nullptr;
        cudaDriverEntryPointQueryResult q;
        cudaGetDriverEntryPointByVersion("cuTensorMapEncodeTiled", &p, 12000, cudaEnableDefault, &q);
        fn = (EncodeFn)p;
    }
    return fn;
}

static void mk_map(CUtensorMap* tm, void* base, uint64_t d0, uint64_t d1, uint64_t d2) {
    cuuint64_t dims[3]    = {(cuuint64_t)d0, (cuuint64_t)d1, (cuuint64_t)d2};
    cuuint64_t strides[2] = {(cuuint64_t)(d0 * 2), (cuuint64_t)(d0 * d1 * 2)};
    cuuint32_t box[3]     = {64u, 128u, 1u};
    cuuint32_t es[3]      = {1u, 1u, 1u};
    get_encode_fn()(tm, CU_TENSOR_MAP_DATA_TYPE_BFLOAT16, 3, base, dims, strides, box, es,
        CU_TENSOR_MAP_INTERLEAVE_NONE, CU_TENSOR_MAP_SWIZZLE_128B,
        CU_TENSOR_MAP_L2_PROMOTION_L2_128B, CU_TENSOR_MAP_FLOAT_OOB_FILL_NONE);
}

// ---------------- host launcher ----------------
extern "C" void kernel_launch(void* const* d_in, const int* in_sizes, int n_in,
                              void* d_out, int out_size) {
    const float* x        = (const float*)d_in[0];
    const float* x0       = (const float*)d_in[1];
    const float* noise    = (const float*)d_in[2];
    const float* lambdas  = (const float*)d_in[3];
    const float* qkv_w    = (const float*)d_in[5];
    const float* c_proj_w = (const float*)d_in[6];
    const float* c_proj_b = (const float*)d_in[7];
    const float* router_w = (const float*)d_in[8];
    const float* router_b = (const float*)d_in[9];
    const float* noise_w  = (const float*)d_in[10];
    const float* noise_b  = (const float*)d_in[11];
    const float* ew1      = (const float*)d_in[12];
    const float* eb1      = (const float*)d_in[13];
    const float* ew2      = (const float*)d_in[14];
    const float* eb2      = (const float*)d_in[15];
    float* out = (float*)d_out;

    void *p_xmix, *p_h, *p_idx, *p_cnt, *p_g0;
    void *p_abf, *p_obf, *p_hbf, *p_h1bf, *p_wqkv, *p_wcp, *p_we1, *p_we2;
    cudaGetSymbolAddress(&p_xmix, g_xmix);
    cudaGetSymbolAddress(&p_h,    g_h);
    cudaGetSymbolAddress(&p_idx,  g_idx);
    cudaGetSymbolAddress(&p_cnt,  g_cnt);
    cudaGetSymbolAddress(&p_g0,   g_g0);
    cudaGetSymbolAddress(&p_abf,  g_abf);
    cudaGetSymbolAddress(&p_obf,  g_obf);
    cudaGetSymbolAddress(&p_hbf,  g_hbf);
    cudaGetSymbolAddress(&p_h1bf, g_h1bf);
    cudaGetSymbolAddress(&p_wqkv, g_wqkv);
    cudaGetSymbolAddress(&p_wcp,  g_wcp);
    cudaGetSymbolAddress(&p_we1,  g_we1);
    cudaGetSymbolAddress(&p_we2,  g_we2);

    bf16* abf_h  = (bf16*)p_abf;   bf16* abf_l  = abf_h  + (size_t)NTOK*CC;
    bf16* obf_h  = (bf16*)p_obf;   bf16* obf_l  = obf_h  + (size_t)NTOK*CC;
    bf16* hbf_h  = (bf16*)p_hbf;   bf16* hbf_l  = hbf_h  + (size_t)NTOK*CC;
    bf16* h1_h   = (bf16*)p_h1bf;  bf16* h1_l   = h1_h   + (size_t)EE*CAPX*HID;
    bf16* wqkv_h = (bf16*)p_wqkv;  bf16* wqkv_l = wqkv_h + (size_t)3*CC*CC;
    bf16* wcp_h  = (bf16*)p_wcp;   bf16* wcp_l  = wcp_h  + (size_t)CC*CC;
    bf16* we1_h  = (bf16*)p_we1;   bf16* we1_l  = we1_h  + (size_t)EE*HID*CC;
    bf16* we2_h  = (bf16*)p_we2;   bf16* we2_l  = we2_h  + (size_t)EE*CC*HID;

    CUtensorMap tmQh, tmQl, tmCh, tmCl, tmE1h, tmE1l, tmE2h, tmE2l;
    mk_map(&tmQh,  wqkv_h, CC, CC, 3);
    mk_map(&tmQl,  wqkv_l, CC, CC, 3);
    mk_map(&tmCh,  wcp_h,  CC, CC, 1);
    mk_map(&tmCl,  wcp_l,  CC, CC, 1);
    mk_map(&tmE1h, we1_h,  CC, HID, EE);
    mk_map(&tmE1l, we1_l,  CC, HID, EE);
    mk_map(&tmE2h, we2_h,  HID, CC, EE);
    mk_map(&tmE2l, we2_l,  HID, CC, EE);

    cudaFuncSetAttribute(gemm_bf<5,false,false>, cudaFuncAttributeMaxDynamicSharedMemorySize, SMEM_TOTAL_TC);
    cudaFuncSetAttribute(gemm_bf<2,false,false>, cudaFuncAttributeMaxDynamicSharedMemorySize, SMEM_TOTAL_TC);
    cudaFuncSetAttribute(gemm_bf<3,true, true >, cudaFuncAttributeMaxDynamicSharedMemorySize, SMEM_TOTAL_TC);
    cudaFuncSetAttribute(gemm_bf<4,false,true >, cudaFuncAttributeMaxDynamicSharedMemorySize, SMEM_TOTAL_TC);
    cudaFuncSetAttribute(attn_tc, cudaFuncAttributeMaxDynamicSharedMemorySize, SMEM_ATT);

    // launch configs: cluster GEMM (cluster + PDL), plain PDL
    cudaLaunchAttribute gattr[2];
    gattr[0].id = cudaLaunchAttributeClusterDimension;
    gattr[0].val.clusterDim.x = 1; gattr[0].val.clusterDim.y = 2; gattr[0].val.clusterDim.z = 1;
    gattr[1].id = cudaLaunchAttributeProgrammaticStreamSerialization;
    gattr[1].val.programmaticStreamSerializationAllowed = 1;
    cudaLaunchConfig_t gcfg = {};
    gcfg.blockDim = dim3(256, 1, 1);
    gcfg.dynamicSmemBytes = SMEM_TOTAL_TC;
    gcfg.attrs = gattr;
    gcfg.numAttrs = 2;
    gcfg.stream = 0;

    cudaLaunchAttribute pattr[1];
    pattr[0].id = cudaLaunchAttributeProgrammaticStreamSerialization;
    pattr[0].val.programmaticStreamSerializationAllowed = 1;
    cudaLaunchConfig_t pcfg = {};
    pcfg.attrs = pattr;
    pcfg.numAttrs = 1;
    pcfg.stream = 0;

    // ---- side stream: rotary tables + deferred weight conversions
    cudaStream_t s2;
    cudaStreamCreateWithFlags(&s2, cudaStreamNonBlocking);
    cudaEvent_t evFork, evRot, evJoinCp, evJoinMoE;
    cudaEventCreateWithFlags(&evFork,    cudaEventDisableTiming);
    cudaEventCreateWithFlags(&evRot,     cudaEventDisableTiming);
    cudaEventCreateWithFlags(&evJoinCp,  cudaEventDisableTiming);
    cudaEventCreateWithFlags(&evJoinMoE, cudaEventDisableTiming);

    cudaEventRecord(evFork, 0);
    cudaStreamWaitEvent(s2, evFork, 0);

    rot_tab_kernel<<<(TT*16 + 255)/256, 256, 0, s2>>>();
    cudaEventRecord(evRot, s2);
    conv_kernel<<<(CC*CC/4 + 255)/256, 256, 0, s2>>>(c_proj_w, wcp_h, wcp_l, (long)CC*CC/4);
    cudaEventRecord(evJoinCp, s2);
    conv_kernel<<<((long)EE*HID*CC/4 + 255)/256, 256, 0, s2>>>(ew1, we1_h, we1_l, (long)EE*HID*CC/4);
    conv_kernel<<<((long)EE*CC*HID/4 + 255)/256, 256, 0, s2>>>(ew2, we2_h, we2_l, (long)EE*CC*HID/4);
    cudaEventRecord(evJoinMoE, s2);

    // main: qkv weight conv + pipeline
    conv_kernel<<<(3*CC*CC/4 + 255)/256, 256>>>(qkv_w, wqkv_h, wqkv_l, (long)3*CC*CC/4);

    pcfg.gridDim = dim3(NTOK, 1, 1);
    pcfg.blockDim = dim3(256, 1, 1);
    pcfg.dynamicSmemBytes = 0;
    cudaLaunchKernelEx(&pcfg, mix_rms_kernel, x, x0, lambdas);

    cudaStreamWaitEvent(0, evRot, 0);   // rot tables ready before qkv epilogue

    gcfg.gridDim = dim3(CC/256, NTOK/128, 3);
    cudaLaunchKernelEx(&gcfg, gemm_bf<5,false,false>,
        (const bf16*)abf_h, (const bf16*)abf_l, 0L,
        (const bf16*)wqkv_h, (const bf16*)wqkv_l, (long)CC*CC,
        tmQh, tmQl,
        (float*)nullptr, (bf16*)nullptr, (bf16*)nullptr, 0L,
        (const float*)nullptr, 0, (const float*)nullptr,
        (const int*)nullptr, (const int*)nullptr, (const float*)nullptr, (int)CC, (int)CC);

    pcfg.gridDim = dim3(TT/128, 2*HH, 1);
    pcfg.blockDim = dim3(256, 1, 1);
    pcfg.dynamicSmemBytes = SMEM_ATT;
    cudaLaunchKernelEx(&pcfg, attn_tc);

    cudaStreamWaitEvent(0, evJoinCp, 0);
    gcfg.gridDim = dim3(CC/256, NTOK/128, 1);
    cudaLaunchKernelEx(&gcfg, gemm_bf<2,false,false>,
        (const bf16*)obf_h, (const bf16*)obf_l, 0L,
        (const bf16*)wcp_h, (const bf16*)wcp_l, 0L,
        tmCh, tmCl,
        out, (bf16*)nullptr, (bf16*)nullptr, 0L,
        c_proj_b, 0, (const float*)p_xmix,
        (const int*)nullptr, (const int*)nullptr, (const float*)nullptr, (int)CC, (int)CC);

    pcfg.gridDim = dim3(NTOK, 1, 1);
    pcfg.blockDim = dim3(256, 1, 1);
    pcfg.dynamicSmemBytes = 0;
    cudaLaunchKernelEx(&pcfg, rms2_kernel, (const float*)out);

    cudaLaunchKernelEx(&pcfg, router_kernel, router_w, router_b, noise_w, noise_b, noise);

    pcfg.gridDim = dim3(1, 1, 1);
    cudaLaunchKernelEx(&pcfg, build_idx_kernel);

    cudaStreamWaitEvent(0, evJoinMoE, 0);

    gcfg.gridDim = dim3(HID/256, CAPX/128, EE);
    cudaLaunchKernelEx(&gcfg, gemm_bf<3,true,true>,
        (const bf16*)hbf_h, (const bf16*)hbf_l, 0L,
        (const bf16*)we1_h, (const bf16*)we1_l, (long)HID*CC,
        tmE1h, tmE1l,
        (float*)nullptr, h1_h, h1_l, (long)CAPX*HID,
        eb1, (int)HID, (const float*)nullptr,
        (const int*)p_idx, (const int*)p_cnt, (const float*)nullptr, (int)HID, (int)CC);

    gcfg.gridDim = dim3(CC/256, CAPX/128, EE);
    cudaLaunchKernelEx(&gcfg, gemm_bf<4,false,true>,
        (const bf16*)h1_h, (const bf16*)h1_l, (long)CAPX*HID,
        (const bf16*)we2_h, (const bf16*)we2_l, (long)CC*HID,
        tmE2h, tmE2l,
        out, (bf16*)nullptr, (bf16*)nullptr, 0L,
        eb2, (int)CC, (const float*)nullptr,
        (const int*)p_idx, (const int*)p_cnt, (const float*)p_g0, (int)CC, (int)HID);

    cudaEventDestroy(evFork);
    cudaEventDestroy(evRot);
    cudaEventDestroy(evJoinCp);
    cudaEventDestroy(evJoinMoE);
    cudaStreamDestroy(s2);
}

// round 17
// speedup vs baseline: 1.0082x; 1.0018x over previous
#include <cuda_runtime.h>
#include <cuda.h>
#include <cuda_bf16.h>
#include <math.h>
#include <stdint.h>

#define NTOK 4096
#define TT   2048
#define CC   1024
#define HH   16
#define HD   64
#define EE   8
#define CAPX 1024
#define HID  4096

#if defined(__CUDA_ARCH__)
# if (__CUDA_ARCH__ >= 1000) && (defined(__CUDA_ARCH_FEAT_SM103_ALL) || defined(__CUDA_ARCH_FEAT_SM100_ALL) || defined(__CUDA_ARCH_SPECIFIC__) || defined(__CUDA_ARCH_FAMILY_SPECIFIC__))
#  define USE_TC 1
# else
#  define USE_TC 0
# endif
#else
# define USE_TC 0
#endif

typedef __nv_bfloat16 bf16;
typedef __nv_bfloat162 bf162;

// PDL: wait for upstream grid completion + memory flush before touching data.
__device__ __forceinline__ void pdl_sync() {
#if defined(__CUDA_ARCH__) && (__CUDA_ARCH__ >= 900)
    cudaGridDependencySynchronize();
#endif
}

// ---------------- scratch ----------------
__device__ float g_xmix[(size_t)NTOK*CC];
__device__ float g_h   [(size_t)NTOK*CC];
__device__ float g_g0  [NTOK];
__device__ int   g_eid [NTOK];
__device__ int   g_idx [EE*CAPX];
__device__ int   g_cnt [EE];
__device__ float g_rotc[TT*16];
__device__ float g_rots[TT*16];
__device__ bf16 g_abf [2][(size_t)NTOK*CC];
__device__ bf16 g_obf [2][(size_t)NTOK*CC];
__device__ bf16 g_hbf [2][(size_t)NTOK*CC];
__device__ bf16 g_qbf [2][(size_t)NTOK*CC];      // [bh][t][d]
__device__ bf16 g_kbf [2][(size_t)NTOK*CC];      // [bh][t][d]
__device__ bf16 g_vT  [2][(size_t)NTOK*CC];      // [bh][d][t]
__device__ __align__(256) bf16 g_h1bf[2][(size_t)EE*CAPX*HID];
__device__ __align__(256) bf16 g_wqkv[2][(size_t)3*CC*CC];
__device__ __align__(256) bf16 g_wcp [2][(size_t)CC*CC];
__device__ __align__(256) bf16 g_we1 [2][(size_t)EE*HID*CC];
__device__ __align__(256) bf16 g_we2 [2][(size_t)EE*CC*HID];

__constant__ float c_rotinv[16] = {
    1.0f, 0.6299605249474366f, 0.39685026299204984f, 0.25f,
    0.15749013123685915f, 0.09921256574801246f, 0.0625f, 0.03937253280921479f,
    0.024803141437003115f, 0.015625f, 0.009843133202303697f, 0.0062007853592507785f,
    0.00390625f, 0.0024607833005759242f, 0.0015501963398126947f, 0.0009765625f
};

// ---------------- helpers ----------------
__device__ __forceinline__ uint32_t smem_u32(const void* p) {
    uint32_t a;
    asm("{ .reg .u64 t; cvta.to.shared.u64 t, %1; cvt.u32.u64 %0, t; }" : "=r"(a) : "l"(p));
    return a;
}
__device__ __forceinline__ uint32_t sw128(uint32_t off) { return off ^ ((off >> 3) & 0x70); }

__device__ __forceinline__ void cpa16(uint32_t d, const void* s) {
    asm volatile("cp.async.cg.shared.global [%0], [%1], 16;" :: "r"(d), "l"(s) : "memory");
}
#define CPA_COMMIT() asm volatile("cp.async.commit_group;" ::: "memory")
#define CPA_WAIT(n)  asm volatile("cp.async.wait_group %0;" :: "n"(n) : "memory")

__device__ __forceinline__ void split4(float4 v, uint2& hv, uint2& lv) {
    bf16 h0 = __float2bfloat16_rn(v.x), h1 = __float2bfloat16_rn(v.y);
    bf16 h2 = __float2bfloat16_rn(v.z), h3 = __float2bfloat16_rn(v.w);
    bf162 hp0; hp0.x = h0; hp0.y = h1;
    bf162 hp1; hp1.x = h2; hp1.y = h3;
    bf162 lp0 = __floats2bfloat162_rn(v.x - __bfloat162float(h0), v.y - __bfloat162float(h1));
    bf162 lp1 = __floats2bfloat162_rn(v.z - __bfloat162float(h2), v.w - __bfloat162float(h3));
    hv.x = *(uint32_t*)&hp0; hv.y = *(uint32_t*)&hp1;
    lv.x = *(uint32_t*)&lp0; lv.y = *(uint32_t*)&lp1;
}

#if USE_TC
__device__ __forceinline__ uint32_t elect_one() {
    uint32_t p;
    asm volatile("{\n\t.reg .pred p;\n\telect.sync _|p, 0xFFFFFFFF;\n\tselp.b32 %0, 1, 0, p;\n\t}" : "=r"(p));
    return p;
}
__device__ __forceinline__ uint32_t ctarank() {
    uint32_t r;
    asm("mov.u32 %0, %%cluster_ctarank;" : "=r"(r));
    return r;
}
#define CLUSTER_SYNC() do { \
    asm volatile("barrier.cluster.arrive.aligned;" ::: "memory"); \
    asm volatile("barrier.cluster.wait.aligned;" ::: "memory"); \
} while (0)
#define MBAR_INIT(addr, cnt) \
    asm volatile("mbarrier.init.shared.b64 [%0], %1;" :: "r"(addr), "r"(cnt) : "memory")
#define MBAR_EXPECT_TX(addr, bytes) \
    asm volatile("mbarrier.arrive.expect_tx.shared.b64 _, [%0], %1;" :: "r"(addr), "r"(bytes) : "memory")
__device__ __forceinline__ void mbar_wait(uint32_t addr, int phase) {
    uint32_t done = 0;
    while (!done) {
        asm volatile("{\n\t.reg .pred p;\n\t"
            "mbarrier.try_wait.parity.acquire.cta.shared::cta.b64 p, [%1], %2, 0x989680;\n\t"
            "selp.b32 %0, 1, 0, p;\n\t}" : "=r"(done) : "r"(addr), "r"(phase) : "memory");
    }
}
#define TMA_MC_3D(smem, map, x, y, zc, mbar, mask) \
    asm volatile("cp.async.bulk.tensor.3d.shared::cluster.global.tile.mbarrier::complete_tx::bytes.multicast::cluster " \
        "[%0], [%1, {%2, %3, %4}], [%5], %6;" \
        :: "r"(smem), "l"(map), "r"(x), "r"(y), "r"(zc), "r"(mbar), "h"((uint16_t)(mask)) : "memory")
#define TC_ALLOC(addr, n) \
    asm volatile("tcgen05.alloc.cta_group::1.sync.aligned.shared::cta.b32 [%0], %1;" :: "r"(addr), "r"(n) : "memory")
#define TC_DEALLOC(tm, n) \
    asm volatile("tcgen05.dealloc.cta_group::1.sync.aligned.b32 %0, %1;" :: "r"(tm), "r"(n))
#define TC_RELINQ() \
    asm volatile("tcgen05.relinquish_alloc_permit.cta_group::1.sync.aligned;")
#define TC_COMMIT(mbar) \
    asm volatile("tcgen05.commit.cta_group::1.mbarrier::arrive::one.shared::cluster.b64 [%0];" :: "r"(mbar) : "memory")
#define TC_COMMIT_MC(mbar, mask) \
    asm volatile("tcgen05.commit.cta_group::1.mbarrier::arrive::one.shared::cluster.multicast::cluster.b64 [%0], %1;" \
        :: "r"(mbar), "h"((uint16_t)(mask)) : "memory")
#define TC_FENCE_AFTER()  asm volatile("tcgen05.fence::after_thread_sync;" ::: "memory")
#define TC_FENCE_BEFORE() asm volatile("tcgen05.fence::before_thread_sync;" ::: "memory")
#define TC_WAIT_LD()      asm volatile("tcgen05.wait::ld.sync.aligned;" ::: "memory")
#define TC_WAIT_ST()      asm volatile("tcgen05.wait::st.sync.aligned;" ::: "memory")

#define TC_LD_X32(r, a) \
    asm volatile("tcgen05.ld.sync.aligned.32x32b.x32.b32 " \
        "{%0,%1,%2,%3,%4,%5,%6,%7,%8,%9,%10,%11,%12,%13,%14,%15," \
        "%16,%17,%18,%19,%20,%21,%22,%23,%24,%25,%26,%27,%28,%29,%30,%31}, [%32];" \
        : "=r"((r)[0]),"=r"((r)[1]),"=r"((r)[2]),"=r"((r)[3]),"=r"((r)[4]),"=r"((r)[5]),"=r"((r)[6]),"=r"((r)[7]), \
          "=r"((r)[8]),"=r"((r)[9]),"=r"((r)[10]),"=r"((r)[11]),"=r"((r)[12]),"=r"((r)[13]),"=r"((r)[14]),"=r"((r)[15]), \
          "=r"((r)[16]),"=r"((r)[17]),"=r"((r)[18]),"=r"((r)[19]),"=r"((r)[20]),"=r"((r)[21]),"=r"((r)[22]),"=r"((r)[23]), \
          "=r"((r)[24]),"=r"((r)[25]),"=r"((r)[26]),"=r"((r)[27]),"=r"((r)[28]),"=r"((r)[29]),"=r"((r)[30]),"=r"((r)[31]) \
        : "r"(a))

#define TC_ST_X32(a, r) \
    asm volatile("tcgen05.st.sync.aligned.32x32b.x32.b32 [%0], " \
        "{%1,%2,%3,%4,%5,%6,%7,%8,%9,%10,%11,%12,%13,%14,%15,%16," \
        "%17,%18,%19,%20,%21,%22,%23,%24,%25,%26,%27,%28,%29,%30,%31,%32};" \
        :: "r"(a), \
           "r"((r)[0]),"r"((r)[1]),"r"((r)[2]),"r"((r)[3]),"r"((r)[4]),"r"((r)[5]),"r"((r)[6]),"r"((r)[7]), \
           "r"((r)[8]),"r"((r)[9]),"r"((r)[10]),"r"((r)[11]),"r"((r)[12]),"r"((r)[13]),"r"((r)[14]),"r"((r)[15]), \
           "r"((r)[16]),"r"((r)[17]),"r"((r)[18]),"r"((r)[19]),"r"((r)[20]),"r"((r)[21]),"r"((r)[22]),"r"((r)[23]), \
           "r"((r)[24]),"r"((r)[25]),"r"((r)[26]),"r"((r)[27]),"r"((r)[28]),"r"((r)[29]),"r"((r)[30]),"r"((r)[31]) \
        : "memory")

__device__ __forceinline__ void mma_ss_bf16(uint32_t d, uint64_t ad, uint64_t bd,
                                            uint32_t idesc, uint32_t en) {
    asm volatile("{\n\t.reg .pred p;\n\tsetp.ne.u32 p, %4, 0;\n\t"
        "tcgen05.mma.cta_group::1.kind::f16 [%0], %1, %2, %3, {%5,%5,%5,%5}, p;\n\t}"
        :: "r"(d), "l"(ad), "l"(bd), "r"(idesc), "r"(en), "r"(0u) : "memory");
}
__device__ __forceinline__ void mma_ts_bf16(uint32_t d, uint32_t a, uint64_t bd,
                                            uint32_t idesc, uint32_t en) {
    asm volatile("{\n\t.reg .pred p;\n\tsetp.ne.u32 p, %4, 0;\n\t"
        "tcgen05.mma.cta_group::1.kind::f16 [%0], [%1], %2, %3, {%5,%5,%5,%5}, p;\n\t}"
        :: "r"(d), "r"(a), "l"(bd), "r"(idesc), "r"(en), "r"(0u) : "memory");
}
__device__ __forceinline__ uint64_t make_desc(uint32_t base) {
    const uint64_t B = (uint64_t(2) << 61) | (uint64_t(1) << 46) | (uint64_t(64) << 32) | (uint64_t(1) << 16);
    return B | ((uint64_t)(base >> 4) & 0x3FFF);
}
#endif // USE_TC

// ---------------- rotary tables ----------------
__global__ void rot_tab_kernel() {
    int idx = blockIdx.x * 256 + threadIdx.x;
    if (idx >= TT * 16) return;
    int t = idx >> 4, j = idx & 15;
    float th = (float)t * c_rotinv[j];
    g_rotc[idx] = cosf(th);
    g_rots[idx] = sinf(th);
}

// ---------------- fp32 -> hi/lo bf16 ----------------
__global__ void conv_kernel(const float* __restrict__ src, bf16* __restrict__ hi,
                            bf16* __restrict__ lo, long n4) {
    long i = (long)blockIdx.x * blockDim.x + threadIdx.x;
    if (i >= n4) return;
    float4 v = ((const float4*)src)[i];
    uint2 hv, lv; split4(v, hv, lv);
    ((uint2*)hi)[i] = hv; ((uint2*)lo)[i] = lv;
}

// ======= bf16 GEMM: 128x256 tile, 3-term split, cluster-2 B TMA-multicast =======
// EPI: 1=+bias 2=+bias+resid 3=sq(relu(+bias)) 4=scatter 5=fused qk-rot / V-transpose
#define A_PL 16384
#define B_PL 32768
#define BUF_BYTES 98304
#define SMEM_TOTAL_TC (1024 + 2*BUF_BYTES)

template<int EPI, bool GATHER, bool SKIP>
__global__ __launch_bounds__(256)
void gemm_bf(const bf16* __restrict__ Ahi, const bf16* __restrict__ Alo, long aStride,
             const bf16* __restrict__ Bhi, const bf16* __restrict__ Blo, long bStride,
             const __grid_constant__ CUtensorMap tmBh,
             const __grid_constant__ CUtensorMap tmBl,
             float* __restrict__ Cf, bf16* __restrict__ Chi, bf16* __restrict__ Clo, long cStride,
             const float* __restrict__ bias, int biasStride,
             const float* __restrict__ resid,
             const int* __restrict__ rowIdx,
             const int* __restrict__ counts,
             const float* __restrict__ g0,
             int Nt, int Kd) {
    extern __shared__ char smem[];
    pdl_sync();   // upstream data (A, rowIdx/counts, resid) fully visible
    const int z = blockIdx.z;
    const int m0 = blockIdx.y * 128, n0 = blockIdx.x * 256;
    int cnt = 0;
    if (SKIP) {
        cnt = counts[z];
        int pairBase = (int)(blockIdx.y & ~1u) * 128;   // pair-level skip (cluster lockstep)
        if (pairBase >= cnt) return;
    }
    bool active = !SKIP || (m0 < cnt);
    int tid = threadIdx.x, wid = tid >> 5, lane = tid & 31;

    const uint32_t OFF_MB = 8, OFF_RID = 64, OFF_TILE = 1024;
    int* s_rid = (int*)(smem + OFF_RID);
    if (tid < 128) {
        int r;
        if (GATHER) r = min(rowIdx[z * CAPX + m0 + tid], NTOK - 1);
        else        r = m0 + tid;
        s_rid[tid] = r;
    }
    const bf16* Ahz = Ahi + (size_t)z * aStride;
    const bf16* Alz = Alo + (size_t)z * aStride;

#if USE_TC
    uint32_t sbase = smem_u32(smem);
    uint32_t rank = ctarank();
    const uint32_t MB0 = sbase + OFF_MB,      MB1 = sbase + OFF_MB + 8;
    const uint32_t BB0 = sbase + OFF_MB + 16, BB1 = sbase + OFF_MB + 24;
    if (tid == 0) {
        MBAR_INIT(MB0, 2); MBAR_INIT(MB1, 2);
        MBAR_INIT(BB0, 1); MBAR_INIT(BB1, 1);
    }
    if (wid == 0) { TC_ALLOC(sbase + 0, 256u); }
    __syncthreads();
    CLUSTER_SYNC();
    uint32_t tmem = *(uint32_t*)(smem + 0);

    const uint32_t idesc = (1u << 4) | (1u << 7) | (1u << 10) | (32u << 17) | (8u << 24); // N=256

    int nchunks = Kd >> 6;

    auto issue_A = [&](int c, uint32_t tb) {
        int k0 = c * 64;
        #pragma unroll
        for (int i = 0; i < 4; i++) {
            int f = tid + i * 256;
            int row = f >> 3, c8 = f & 7;
            uint32_t so = sw128((uint32_t)(row * 128 + c8 * 16));
            size_t aoff = (size_t)s_rid[row] * Kd + k0 + c8 * 8;
            cpa16(tb + so,        Ahz + aoff);
            cpa16(tb + A_PL + so, Alz + aoff);
        }
        CPA_COMMIT();
    };
    auto issue_B = [&](int c, int buf) {
        if (tid != 0) return;
        uint32_t tb = sbase + OFF_TILE + (uint32_t)buf * BUF_BYTES;
        uint32_t bb = buf ? BB1 : BB0;
        MBAR_EXPECT_TX(bb, 65536u);
        uint32_t soff = rank ? 16384u : 0u;
        int k0 = c * 64;
        int ycoord = n0 + (int)rank * 128;
        TMA_MC_3D(tb + 2 * A_PL + soff,        &tmBh, k0, ycoord, z, bb, 3);
        TMA_MC_3D(tb + 2 * A_PL + B_PL + soff, &tmBl, k0, ycoord, z, bb, 3);
    };

    issue_A(0, sbase + OFF_TILE);
    issue_B(0, 0);

    int ph0 = 0, ph1 = 0, pb0 = 0, pb1 = 0;

    for (int c = 0; c < nchunks; c++) {
        int buf = c & 1;
        uint32_t tb = sbase + OFF_TILE + buf * BUF_BYTES;
        if (c + 1 < nchunks) {
            if (c >= 1) {
                if ((buf ^ 1) == 0) { mbar_wait(MB0, ph0); ph0 ^= 1; }
                else                { mbar_wait(MB1, ph1); ph1 ^= 1; }
            }
            issue_A(c + 1, sbase + OFF_TILE + (buf ^ 1) * BUF_BYTES);
            issue_B(c + 1, buf ^ 1);
            CPA_WAIT(1);
        } else {
            CPA_WAIT(0);
        }
        if (buf == 0) { mbar_wait(BB0, pb0); pb0 ^= 1; }
        else          { mbar_wait(BB1, pb1); pb1 ^= 1; }
        asm volatile("fence.proxy.async.shared::cta;" ::: "memory");
        __syncthreads();
        if (wid == 0) {
            if (elect_one()) {
                uint64_t ah = make_desc(tb);
                uint64_t al = make_desc(tb + A_PL);
                uint64_t bh = make_desc(tb + 2 * A_PL);
                uint64_t bl = make_desc(tb + 2 * A_PL + B_PL);
                #pragma unroll
                for (int ks = 0; ks < 4; ks++) {
                    uint64_t o = ks * 2;
                    mma_ss_bf16(tmem, ah + o, bh + o, idesc, (c > 0 || ks > 0) ? 1u : 0u);
                    mma_ss_bf16(tmem, ah + o, bl + o, idesc, 1u);
                    mma_ss_bf16(tmem, al + o, bh + o, idesc, 1u);
                }
                TC_COMMIT_MC(buf == 0 ? MB0 : MB1, 3);
            }
        }
    }
    mbar_wait(MB0, ph0);
    mbar_wait(MB1, ph1);
    TC_FENCE_AFTER();
    CLUSTER_SYNC();

    int colbase = (wid >> 2) * 128;
    int row = (wid & 3) * 32 + lane;
    int gm = m0 + row;

    if (EPI == 5) {
        if (z < 2) {
            int t = gm & (TT - 1), bb = gm >> 11;
            bf16* hip = z ? g_kbf[0] : g_qbf[0];
            bf16* lop = z ? g_kbf[1] : g_qbf[1];
            const float* ctab = g_rotc + t * 16;
            const float* stab = g_rots + t * 16;
            float cv[16], sv[16];
            #pragma unroll
            for (int d = 0; d < 16; d += 4) {
                float4 c4 = *(const float4*)(ctab + d);
                float4 s4 = *(const float4*)(stab + d);
                cv[d] = c4.x; cv[d+1] = c4.y; cv[d+2] = c4.z; cv[d+3] = c4.w;
                sv[d] = s4.x; sv[d+1] = s4.y; sv[d+2] = s4.z; sv[d+3] = s4.w;
            }
            #pragma unroll
            for (int g2 = 0; g2 < 2; g2++) {
                int co = colbase + g2 * 64;
                uint32_t dr[64];
                TC_LD_X32(dr,      tmem + co);
                TC_LD_X32(dr + 32, tmem + co + 32);
                TC_WAIT_LD();
                float v[64]; float ss = 0.f;
                #pragma unroll
                for (int j = 0; j < 64; j++) { v[j] = __uint_as_float(dr[j]); ss += v[j] * v[j]; }
                float sc = rsqrtf(ss * (1.0f / HD) + 1e-6f);
                float o[64];
                #pragma unroll
                for (int d = 0; d < 16; d++) {
                    float x1 = v[d] * sc, x2 = v[d + 32] * sc;
                    o[d]      =  x1 * cv[d] + x2 * sv[d];
                    o[d + 32] = -x1 * sv[d] + x2 * cv[d];
                }
                #pragma unroll
                for (int d = 16; d < 32; d++) {
                    o[d]      = v[d] * sc;
                    o[d + 32] = v[d + 32] * sc;
                }
                int hh = (n0 + co) >> 6;
                size_t basep = ((size_t)(bb * HH + hh) * TT + t) * HD;
                #pragma unroll
                for (int j = 0; j < 64; j += 4) {
                    float4 f4; f4.x = o[j]; f4.y = o[j+1]; f4.z = o[j+2]; f4.w = o[j+3];
                    uint2 hv, lv; split4(f4, hv, lv);
                    *(uint2*)(hip + basep + j) = hv;
                    *(uint2*)(lop + basep + j) = lv;
                }
            }
        } else {
            const int TP = 136;
            bf16* sh = (bf16*)(smem + OFF_TILE);
            __syncthreads();
            #pragma unroll
            for (int g2 = 0; g2 < 2; g2++) {
                int co = colbase + g2 * 64;
                uint32_t dr[64];
                TC_LD_X32(dr,      tmem + co);
                TC_LD_X32(dr + 32, tmem + co + 32);
                TC_WAIT_LD();
                #pragma unroll
                for (int j = 0; j < 64; j++) {
                    float vv = __uint_as_float(dr[j]);
                    bf16 hv = __float2bfloat16_rn(vv);
                    bf16 lv = __float2bfloat16_rn(vv - __bfloat162float(hv));
                    sh[(size_t)(co + j) * TP + row]       = hv;
                    sh[(size_t)(256 + co + j) * TP + row] = lv;
                }
            }
            __syncthreads();
            int bb2 = m0 >> 11, t0 = m0 & (TT - 1);
            int col = n0 + tid;
            int hh = col >> 6, dd = col & 63;
            size_t dst = ((size_t)((bb2 * HH + hh) * HD + dd)) * TT + t0;
            const bf16* s0 = sh + (size_t)tid * TP;
            const bf16* s1 = sh + (size_t)(256 + tid) * TP;
            #pragma unroll
            for (int q = 0; q < 128; q += 8) {
                *(uint4*)(g_vT[0] + dst + q) = *(const uint4*)(s0 + q);
                *(uint4*)(g_vT[1] + dst + q) = *(const uint4*)(s1 + q);
            }
        }
    } else {
        int token = 0; float gg = 0.f; bool valid4 = active;
        if (EPI == 4) {
            valid4 = active && (gm < cnt);
            if (valid4) { token = rowIdx[z * CAPX + gm]; gg = g0[token]; }
        }
        #pragma unroll
        for (int g2 = 0; g2 < 2; g2++) {
            int co = colbase + g2 * 64;
            uint32_t dr[64];
            TC_LD_X32(dr,      tmem + co);
            TC_LD_X32(dr + 32, tmem + co + 32);
            TC_WAIT_LD();

            const float* bp = (EPI >= 1) ? (bias + (size_t)z * biasStride + n0 + co) : nullptr;
            if (EPI == 3) {
                if (active) {
                    bf16* chp = Chi + (size_t)z * cStride + (size_t)gm * Nt + n0 + co;
                    bf16* clp = Clo + (size_t)z * cStride + (size_t)gm * Nt + n0 + co;
                    #pragma unroll
                    for (int j = 0; j < 64; j += 4) {
                        float4 v;
                        float t0 = __uint_as_float(dr[j+0]) + bp[j+0];
                        float t1 = __uint_as_float(dr[j+1]) + bp[j+1];
                        float t2 = __uint_as_float(dr[j+2]) + bp[j+2];
                        float t3 = __uint_as_float(dr[j+3]) + bp[j+3];
                        v.x = t0 > 0.f ? t0*t0 : 0.f; v.y = t1 > 0.f ? t1*t1 : 0.f;
                        v.z = t2 > 0.f ? t2*t2 : 0.f; v.w = t3 > 0.f ? t3*t3 : 0.f;
                        uint2 hv, lv; split4(v, hv, lv);
                        *(uint2*)(chp + j) = hv; *(uint2*)(clp + j) = lv;
                    }
                }
            } else if (EPI == 4) {
                if (valid4) {
                    float* op = Cf + (size_t)token * Nt + n0 + co;
                    #pragma unroll
                    for (int j = 0; j < 64; j += 4) {
                        float4 o = *(float4*)(op + j);
                        o.x += gg * (__uint_as_float(dr[j+0]) + bp[j+0]);
                        o.y += gg * (__uint_as_float(dr[j+1]) + bp[j+1]);
                        o.z += gg * (__uint_as_float(dr[j+2]) + bp[j+2]);
                        o.w += gg * (__uint_as_float(dr[j+3]) + bp[j+3]);
                        *(float4*)(op + j) = o;
                    }
                }
            } else {
                const float* rp = (EPI == 2) ? (resid + (size_t)gm * Nt + n0 + co) : nullptr;
                float* cp = Cf + (size_t)z * cStride + (size_t)gm * Nt + n0 + co;
                #pragma unroll
                for (int j = 0; j < 64; j += 4) {
                    float vv[4];
                    #pragma unroll
                    for (int q = 0; q < 4; q++) {
                        float t = __uint_as_float(dr[j + q]);
                        if (EPI == 1)      t += bp[j + q];
                        else if (EPI == 2) t += bp[j + q] + rp[j + q];
                        vv[q] = t;
                    }
                    float4 v4; v4.x = vv[0]; v4.y = vv[1]; v4.z = vv[2]; v4.w = vv[3];
                    *(float4*)(cp + j) = v4;
                }
            }
        }
    }

    TC_FENCE_BEFORE();
    __syncthreads();
    if (wid == 0) { TC_RELINQ(); TC_DEALLOC(tmem, 256u); }

#else  // SIMT fallback (non-arch-specific pass; never selected on GB300)
    const bf16* Bhz = Bhi + (size_t)z * bStride;
    const bf16* Blz = Blo + (size_t)z * bStride;
    float* As = (float*)(smem + OFF_TILE);
    float* Bs = (float*)(smem + OFF_TILE + 16 * 128 * 4);
    float* Stg = (float*)(smem + OFF_TILE + 32 * 128 * 4);
    __syncthreads();
    int tm = (tid >> 4) * 8, tn = (tid & 15) * 8;
    for (int nsub = 0; nsub < 2; nsub++) {
        int n0s = n0 + nsub * 128;
        float acc[8][8];
        #pragma unroll
        for (int i = 0; i < 8; i++)
            #pragma unroll
            for (int j = 0; j < 8; j++) acc[i][j] = 0.f;
        for (int k0 = 0; k0 < Kd; k0 += 16) {
            #pragma unroll
            for (int i = 0; i < 2; i++) {
                int f = tid + i * 256;
                int rw_ = f >> 2, c4 = (f & 3) * 4;
                #pragma unroll
                for (int q = 0; q < 4; q++) {
                    size_t ao = (size_t)s_rid[rw_] * Kd + k0 + c4 + q;
                    size_t bo = (size_t)(n0s + rw_) * Kd + k0 + c4 + q;
                    As[(c4+q)*128 + rw_] = __bfloat162float(Ahz[ao]) + __bfloat162float(Alz[ao]);
                    Bs[(c4+q)*128 + rw_] = __bfloat162float(Bhz[bo]) + __bfloat162float(Blz[bo]);
                }
            }
            __syncthreads();
            #pragma unroll
            for (int kk = 0; kk < 16; kk++) {
                float a_[8], b_[8];
                #pragma unroll
                for (int q = 0; q < 8; q++) { a_[q] = As[kk*128 + tm + q]; b_[q] = Bs[kk*128 + tn + q]; }
                #pragma unroll
                for (int i = 0; i < 8; i++)
                    #pragma unroll
                    for (int j = 0; j < 8; j++)
                        acc[i][j] += a_[i] * b_[j];
            }
            __syncthreads();
        }
        if (EPI == 5) {
            #pragma unroll
            for (int i = 0; i < 8; i++)
                #pragma unroll
                for (int j = 0; j < 8; j++)
                    Stg[(tm + i) * 132 + tn + j] = acc[i][j];
            __syncthreads();
            int r = tid >> 1, hseg = tid & 1;
            int gmr = m0 + r;
            int t = gmr & (TT - 1), bb = gmr >> 11;
            float v[64];
            #pragma unroll
            for (int j = 0; j < 64; j++) v[j] = Stg[r * 132 + hseg * 64 + j];
            int col0 = n0s + hseg * 64;
            int hh = col0 >> 6;
            if (z < 2) {
                float ss = 0.f;
                #pragma unroll
                for (int j = 0; j < 64; j++) ss += v[j] * v[j];
                float sc = rsqrtf(ss * (1.0f / HD) + 1e-6f);
                bf16* hip = z ? g_kbf[0] : g_qbf[0];
                bf16* lop = z ? g_kbf[1] : g_qbf[1];
                size_t basep = ((size_t)(bb * HH + hh) * TT + t) * HD;
                #pragma unroll
                for (int d = 0; d < 32; d++) {
                    float x1 = v[d] * sc, x2 = v[d + 32] * sc;
                    float cth = (d < 16) ? g_rotc[t * 16 + d] : 1.f;
                    float sth = (d < 16) ? g_rots[t * 16 + d] : 0.f;
                    float y1 = x1 * cth + x2 * sth;
                    float y2 = -x1 * sth + x2 * cth;
                    bf16 h1 = __float2bfloat16_rn(y1), h2 = __float2bfloat16_rn(y2);
                    hip[basep + d] = h1; hip[basep + d + 32] = h2;
                    lop[basep + d] = __float2bfloat16_rn(y1 - __bfloat162float(h1));
                    lop[basep + d + 32] = __float2bfloat16_rn(y2 - __bfloat162float(h2));
                }
            } else {
                #pragma unroll
                for (int d = 0; d < 64; d++) {
                    float vv = v[d];
                    bf16 hv = __float2bfloat16_rn(vv);
                    size_t dst = ((size_t)((bb * HH + hh) * HD + d)) * TT + t;
                    g_vT[0][dst] = hv;
                    g_vT[1][dst] = __float2bfloat16_rn(vv - __bfloat162float(hv));
                }
            }
            __syncthreads();
        } else {
            #pragma unroll
            for (int i = 0; i < 8; i++) {
                int gmr = m0 + tm + i;
                bool act = !SKIP || (m0 < cnt);
                #pragma unroll
                for (int j = 0; j < 8; j++) {
                    float t = acc[i][j];
                    int col = n0s + tn + j;
                    if (EPI >= 1 && EPI <= 4) t += bias[(size_t)z * biasStride + col];
                    if (EPI == 2) t += resid[(size_t)gmr * Nt + col];
                    if (EPI == 3) {
                        if (act) {
                            t = t > 0.f ? t * t : 0.f;
                            bf16 hv = __float2bfloat16_rn(t);
                            Chi[(size_t)z * cStride + (size_t)gmr * Nt + col] = hv;
                            Clo[(size_t)z * cStride + (size_t)gmr * Nt + col] = __float2bfloat16_rn(t - __bfloat162float(hv));
                        }
                    } else if (EPI == 4) {
                        if (act && gmr < cnt) {
                            int token = rowIdx[z * CAPX + gmr];
                            atomicAdd(&Cf[(size_t)token * Nt + col], g0[token] * t);
                        }
                    } else {
                        Cf[(size_t)z * cStride + (size_t)gmr * Nt + col] = t;
                    }
                }
            }
        }
    }
#endif
}

// ---------------- block reduce ----------------
__device__ __forceinline__ float blockReduceSum(float v) {
    __shared__ float sh[32];
    int lane = threadIdx.x & 31, w = threadIdx.x >> 5;
    #pragma unroll
    for (int o = 16; o; o >>= 1) v += __shfl_down_sync(0xffffffffu, v, o);
    if (lane == 0) sh[w] = v;
    __syncthreads();
    int nw = blockDim.x >> 5;
    if (w == 0) {
        v = (lane < nw) ? sh[lane] : 0.f;
        #pragma unroll
        for (int o = 16; o; o >>= 1) v += __shfl_down_sync(0xffffffffu, v, o);
        if (lane == 0) sh[0] = v;
    }
    __syncthreads();
    return sh[0];
}

// ---------------- 1) residual mix + rmsnorm ----------------
__global__ void mix_rms_kernel(const float* __restrict__ x, const float* __restrict__ x0,
                               const float* __restrict__ lambdas) {
    pdl_sync();
    int row = blockIdx.x;
    float l0 = lambdas[0], l1 = lambdas[1];
    size_t off = (size_t)row * CC + threadIdx.x * 4;
    float4 a = *(const float4*)(x + off);
    float4 b = *(const float4*)(x0 + off);
    float4 v;
    v.x = l0*a.x + l1*b.x; v.y = l0*a.y + l1*b.y;
    v.z = l0*a.z + l1*b.z; v.w = l0*a.w + l1*b.w;
    *(float4*)(g_xmix + off) = v;
    float ss = v.x*v.x + v.y*v.y + v.z*v.z + v.w*v.w;
    float tot = blockReduceSum(ss);
    float sc = rsqrtf(tot * (1.0f/CC) + 1e-6f);
    float4 o; o.x = v.x*sc; o.y = v.y*sc; o.z = v.z*sc; o.w = v.w*sc;
    uint2 hv, lv; split4(o, hv, lv);
    *(uint2*)(&g_abf[0][off]) = hv;
    *(uint2*)(&g_abf[1][off]) = lv;
}

// ---------------- 6) rmsnorm of x2 ----------------
__global__ void rms2_kernel(const float* __restrict__ src) {
    pdl_sync();
    int row = blockIdx.x;
    size_t off = (size_t)row * CC + threadIdx.x * 4;
    float4 v = *(const float4*)(src + off);
    float ss = v.x*v.x + v.y*v.y + v.z*v.z + v.w*v.w;
    float tot = blockReduceSum(ss);
    float sc = rsqrtf(tot * (1.0f/CC) + 1e-6f);
    float4 o; o.x = v.x*sc; o.y = v.y*sc; o.z = v.z*sc; o.w = v.w*sc;
    *(float4*)(g_h + off) = o;
    uint2 hv, lv; split4(o, hv, lv);
    *(uint2*)(&g_hbf[0][off]) = hv;
    *(uint2*)(&g_hbf[1][off]) = lv;
}

// ---------------- 4) pipelined tensor-core causal attention ----------------
#define AT_QHI 2048
#define AT_QLO (AT_QHI + 16384)
#define AT_KBUF 34816
#define AT_VBUF (AT_KBUF + 3*32768)
#define SMEM_ATT (AT_VBUF + 2*32768)
#define AT_L2 128

__global__ __launch_bounds__(256) void attn_tc() {
    extern __shared__ char smem[];
    int qtile = gridDim.x - 1 - blockIdx.x;   // LPT
    int bh = blockIdx.y;
    int b = bh >> 4, h = bh & 15;
    int q0 = qtile * 128;
    int tid = threadIdx.x, wid = tid >> 5, lane = tid & 31;
    int half = wid >> 2;
    int row = (wid & 3) * 32 + lane;

    const bf16* qh_g = g_qbf[0] + ((size_t)bh * TT + q0) * HD;
    const bf16* ql_g = g_qbf[1] + ((size_t)bh * TT + q0) * HD;

#if USE_TC
    uint32_t sbase = smem_u32(smem);
    const uint32_t MBS = sbase + 8, MBA = sbase + 16;
    float* l2s = (float*)(smem + AT_L2);
    if (tid == 0) { MBAR_INIT(MBS, 1); MBAR_INIT(MBA, 1); }
    if (wid == 0) { TC_ALLOC(sbase + 0, 512u); }   // independent prologue under PDL
    pdl_sync();                                    // qkv GEMM outputs now visible

    auto load_K = [&](int kt) {
        uint32_t kb = sbase + AT_KBUF + (uint32_t)(kt % 3) * 32768;
        const bf16* kh_g = g_kbf[0] + ((size_t)bh * TT + kt * 128) * HD;
        const bf16* kl_g = g_kbf[1] + ((size_t)bh * TT + kt * 128) * HD;
        #pragma unroll
        for (int i = 0; i < 4; i++) {
            int f = tid + i * 256;
            int r = f >> 3, c8 = f & 7;
            uint32_t so = sw128((uint32_t)(r * 128 + c8 * 16));
            cpa16(kb + so,         kh_g + (size_t)r * HD + c8 * 8);
            cpa16(kb + 16384 + so, kl_g + (size_t)r * HD + c8 * 8);
        }
    };
    auto load_V = [&](int kt) {
        uint32_t vb = sbase + AT_VBUF + (uint32_t)(kt & 1) * 32768;
        const bf16* vh_g = g_vT[0] + (size_t)bh * HD * TT + kt * 128;
        const bf16* vl_g = g_vT[1] + (size_t)bh * HD * TT + kt * 128;
        #pragma unroll
        for (int i = 0; i < 4; i++) {
            int f = tid + i * 256;
            int d = f >> 4, c16 = f & 15;
            uint32_t byte = (uint32_t)((d >> 3) * 1024 + (c16 >> 3) * 8192 + (d & 7) * 128 + (c16 & 7) * 16);
            uint32_t so = sw128(byte);
            cpa16(vb + so,         vh_g + (size_t)d * TT + c16 * 8);
            cpa16(vb + 16384 + so, vl_g + (size_t)d * TT + c16 * 8);
        }
    };

    {
        #pragma unroll
        for (int i = 0; i < 4; i++) {
            int f = tid + i * 256;
            int r = f >> 3, c8 = f & 7;
            uint32_t so = sw128((uint32_t)(r * 128 + c8 * 16));
            cpa16(sbase + AT_QHI + so, qh_g + (size_t)r * HD + c8 * 8);
            cpa16(sbase + AT_QLO + so, ql_g + (size_t)r * HD + c8 * 8);
        }
        load_K(0);
        load_V(0);
        CPA_COMMIT();
        if (qtile >= 1) { load_K(1); CPA_COMMIT(); }
    }
    __syncthreads();
    uint32_t tmem = *(uint32_t*)(smem + 0);
    const uint32_t S0 = 0, O_OFF = 256, P0 = 320;
    const uint32_t IDS = (1u<<4)|(1u<<7)|(1u<<10)|(16u<<17)|(8u<<24);  // N=128
    const uint32_t IDA = (1u<<4)|(1u<<7)|(1u<<10)|( 8u<<17)|(8u<<24);  // N=64

    CPA_WAIT(0);
    asm volatile("fence.proxy.async.shared::cta;" ::: "memory");
    __syncthreads();

    uint64_t qhd = make_desc(sbase + AT_QHI);
    uint64_t qld = make_desc(sbase + AT_QLO);

    auto issue_S = [&](int kt) {
        uint32_t kb = sbase + AT_KBUF + (uint32_t)(kt % 3) * 32768;
        uint64_t kh = make_desc(kb);
        uint64_t kl = make_desc(kb + 16384);
        uint32_t sd = tmem + S0 + (uint32_t)(kt & 1) * 128;
        #pragma unroll
        for (int ks = 0; ks < 4; ks++) {
            uint64_t o = ks * 2;
            mma_ss_bf16(sd, qhd + o, kh + o, IDS, ks > 0 ? 1u : 0u);
            mma_ss_bf16(sd, qhd + o, kl + o, IDS, 1u);
            mma_ss_bf16(sd, qld + o, kh + o, IDS, 1u);
        }
        TC_COMMIT(MBS);
    };

    if (wid == 0 && elect_one()) issue_S(0);

    float l = 0.f;
    int phS = 0, phA = 0;

    for (int kt = 0; kt <= qtile; kt++) {
        int sbuf = kt & 1;
        if (kt + 2 <= qtile) { load_K(kt + 2); CPA_COMMIT(); }
        mbar_wait(MBS, phS); phS ^= 1;
        TC_FENCE_AFTER();
        if (kt + 2 <= qtile) { CPA_WAIT(1); } else { CPA_WAIT(0); }
        asm volatile("fence.proxy.async.shared::cta;" ::: "memory");
        __syncthreads();
        if (kt < qtile && wid == 0) {
            if (elect_one()) { TC_FENCE_AFTER(); issue_S(kt + 1); }
        }

        uint32_t sr[64];
        TC_LD_X32(sr, tmem + S0 + sbuf * 128 + half * 64);
        TC_WAIT_LD();
        TC_LD_X32(sr + 32, tmem + S0 + sbuf * 128 + half * 64 + 32);

        int qg = q0 + row;
        int kbase = kt * 128 + half * 64;
        bool maskTile = (kt == qtile);
        uint32_t pw[32];
        float lacc = 0.f;
        #pragma unroll
        for (int j2 = 0; j2 < 16; j2++) {
            float s0v = __uint_as_float(sr[2*j2])   * 0.125f;
            float s1v = __uint_as_float(sr[2*j2+1]) * 0.125f;
            float p0 = __expf(s0v), p1 = __expf(s1v);
            if (maskTile) {
                if (kbase + 2*j2     > qg) p0 = 0.f;
                if (kbase + 2*j2 + 1 > qg) p1 = 0.f;
            }
            bf162 pb = __floats2bfloat162_rn(p0, p1);
            lacc += __bfloat162float(pb.x) + __bfloat162float(pb.y);
            pw[j2] = *(uint32_t*)&pb;
        }
        TC_WAIT_LD();
        #pragma unroll
        for (int j2 = 16; j2 < 32; j2++) {
            float s0v = __uint_as_float(sr[2*j2])   * 0.125f;
            float s1v = __uint_as_float(sr[2*j2+1]) * 0.125f;
            float p0 = __expf(s0v), p1 = __expf(s1v);
            if (maskTile) {
                if (kbase + 2*j2     > qg) p0 = 0.f;
                if (kbase + 2*j2 + 1 > qg) p1 = 0.f;
            }
            bf162 pb = __floats2bfloat162_rn(p0, p1);
            lacc += __bfloat162float(pb.x) + __bfloat162float(pb.y);
            pw[j2] = *(uint32_t*)&pb;
        }
        l += lacc;

        if (kt > 0) { mbar_wait(MBA, phA); phA ^= 1; }

        if (kt < qtile) { load_V(kt + 1); CPA_COMMIT(); }

        TC_ST_X32(tmem + P0 + sbuf * 64 + half * 32 + ((uint32_t)(wid & 3) << 21), pw);
        TC_WAIT_ST();
        TC_FENCE_BEFORE();
        __syncthreads();

        if (wid == 0 && elect_one()) {
            TC_FENCE_AFTER();
            uint32_t vb = sbase + AT_VBUF + (uint32_t)sbuf * 32768;
            uint64_t vh = make_desc(vb);
            uint64_t vl = make_desc(vb + 16384);
            #pragma unroll
            for (int ks = 0; ks < 8; ks++) {
                uint64_t vo = (uint64_t)((ks & 3) * 2 + (ks >> 2) * 512);
                uint32_t at = tmem + P0 + sbuf * 64 + ks * 8;
                mma_ts_bf16(tmem + O_OFF, at, vh + vo, IDA, (kt > 0 || ks > 0) ? 1u : 0u);
                mma_ts_bf16(tmem + O_OFF, at, vl + vo, IDA, 1u);
            }
            TC_COMMIT(MBA);
        }
    }
    mbar_wait(MBA, phA);
    TC_FENCE_AFTER();

    l2s[half * 128 + row] = l;
    __syncthreads();
    float inv = 1.f / (l2s[row] + l2s[128 + row]);

    uint32_t od[32];
    TC_LD_X32(od, tmem + O_OFF + half * 32);
    TC_WAIT_LD();
    int token = b * TT + q0 + row;
    bf16* ohp = g_obf[0] + (size_t)token * CC + h * HD + half * 32;
    bf16* olp = g_obf[1] + (size_t)token * CC + h * HD + half * 32;
    #pragma unroll
    for (int j = 0; j < 32; j += 4) {
        float4 v;
        v.x = __uint_as_float(od[j+0]) * inv;
        v.y = __uint_as_float(od[j+1]) * inv;
        v.z = __uint_as_float(od[j+2]) * inv;
        v.w = __uint_as_float(od[j+3]) * inv;
        uint2 hv, lv; split4(v, hv, lv);
        *(uint2*)(ohp + j) = hv; *(uint2*)(olp + j) = lv;
    }
    TC_FENCE_BEFORE();
    __syncthreads();
    if (wid == 0) { TC_RELINQ(); TC_DEALLOC(tmem, 512u); }

#else // SIMT fallback attention
    pdl_sync();
    for (int qq = tid; qq < 128; qq += 256) {
        int qg = q0 + qq;
        float q[HD], o[HD];
        #pragma unroll
        for (int d = 0; d < HD; d++) {
            q[d] = (__bfloat162float(qh_g[(size_t)qq*HD+d]) + __bfloat162float(ql_g[(size_t)qq*HD+d])) * 0.125f;
            o[d] = 0.f;
        }
        float l = 0.f;
        for (int k = 0; k <= qg; k++) {
            const bf16* kh_g = g_kbf[0] + ((size_t)bh * TT + k) * HD;
            const bf16* kl_g = g_kbf[1] + ((size_t)bh * TT + k) * HD;
            float s = 0.f;
            #pragma unroll
            for (int d = 0; d < HD; d++)
                s += q[d] * (__bfloat162float(kh_g[d]) + __bfloat162float(kl_g[d]));
            float p = __expf(s);
            l += p;
            #pragma unroll
            for (int d = 0; d < HD; d++) {
                size_t vo = ((size_t)bh * HD + d) * TT + k;
                o[d] += p * (__bfloat162float(g_vT[0][vo]) + __bfloat162float(g_vT[1][vo]));
            }
        }
        float inv = 1.f / l;
        int token = b * TT + qg;
        #pragma unroll
        for (int d = 0; d < HD; d++) {
            float v = o[d] * inv;
            bf16 hv = __float2bfloat16_rn(v);
            g_obf[0][(size_t)token * CC + h * HD + d] = hv;
            g_obf[1][(size_t)token * CC + h * HD + d] = __float2bfloat16_rn(v - __bfloat162float(hv));
        }
    }
#endif
}

// ---------------- 7) router ----------------
__global__ void router_kernel(const float* __restrict__ rw, const float* __restrict__ rb,
                              const float* __restrict__ nw, const float* __restrict__ nb,
                              const float* __restrict__ noise) {
    pdl_sync();
    int n = blockIdx.x;
    int w = threadIdx.x >> 5, lane = threadIdx.x & 31;
    const float* hr = g_h + (size_t)n * CC;
    const float* wr = rw + (size_t)w * CC;
    const float* wn = nw + (size_t)w * CC;
    float s1 = 0.f, s2 = 0.f;
    for (int c = lane * 4; c < CC; c += 128) {
        float4 hv = *(const float4*)(hr + c);
        float4 r4 = *(const float4*)(wr + c);
        float4 n4 = *(const float4*)(wn + c);
        s1 += hv.x*r4.x + hv.y*r4.y + hv.z*r4.z + hv.w*r4.w;
        s2 += hv.x*n4.x + hv.y*n4.y + hv.z*n4.z + hv.w*n4.w;
    }
    #pragma unroll
    for (int o = 16; o; o >>= 1) {
        s1 += __shfl_xor_sync(0xffffffffu, s1, o);
        s2 += __shfl_xor_sync(0xffffffffu, s2, o);
    }
    __shared__ float lg[8], nl[8];
    if (lane == 0) { lg[w] = s1 + rb[w]; nl[w] = s2 + nb[w]; }
    __syncthreads();
    if (threadIdx.x == 0) {
        float nv[8];
        #pragma unroll
        for (int e = 0; e < 8; e++) {
            float xn = nl[e];
            float sp = (xn > 20.f) ? xn : log1pf(expf(xn));
            nv[e] = lg[e] + noise[(size_t)n * EE + e] * sp;
        }
        int i0 = 0; float v0 = nv[0];
        #pragma unroll
        for (int e = 1; e < 8; e++) if (nv[e] > v0) { v0 = nv[e]; i0 = e; }
        float v1 = -1e30f;
        #pragma unroll
        for (int e = 0; e < 8; e++) if (e != i0 && nv[e] > v1) { v1 = nv[e]; }
        float e1 = expf(v1 - v0);
        g_g0[n] = 1.f / (1.f + e1);
        g_eid[n] = i0;
    }
}

// ---------------- 8) per-expert capacity lists ----------------
__global__ void build_idx_kernel() {
    pdl_sync();
    int w = threadIdx.x >> 5, lane = threadIdx.x & 31;
    int count = 0;
    for (int base = 0; base < NTOK; base += 32) {
        int t = base + lane;
        bool p = (g_eid[t] == w);
        unsigned msk = __ballot_sync(0xffffffffu, p);
        int pos = count + __popc(msk & ((1u << lane) - 1u));
        if (p && pos < CAPX) g_idx[w * CAPX + pos] = t;
        count += __popc(msk);
    }
    int c = min(count, CAPX);
    if (lane == 0) g_cnt[w] = c;
    for (int s = c + lane; s < CAPX; s += 32) g_idx[w * CAPX + s] = NTOK;
}

// ---------------- host: tensormap encode via driver entry point ----------------
typedef CUresult (*EncodeFn)(CUtensorMap*, CUtensorMapDataType, cuuint32_t, void*,
    const cuuint64_t*, const cuuint64_t*, const cuuint32_t*, const cuuint32_t*,
    CUtensorMapInterleave, CUtensorMapSwizzle, CUtensorMapL2promotion, CUtensorMapFloatOOBfill);

static EncodeFn get_encode_fn() {
    static EncodeFn fn = nullptr;
    if (!fn) {
        void* p = nullptr;
        cudaDriverEntryPointQueryResult q;
        cudaGetDriverEntryPointByVersion("cuTensorMapEncodeTiled", &p, 12000, cudaEnableDefault, &q);
        fn = (EncodeFn)p;
    }
    return fn;
}

static void mk_map(CUtensorMap* tm, void* base, uint64_t d0, uint64_t d1, uint64_t d2) {
    cuuint64_t dims[3]    = {(cuuint64_t)d0, (cuuint64_t)d1, (cuuint64_t)d2};
    cuuint64_t strides[2] = {(cuuint64_t)(d0 * 2), (cuuint64_t)(d0 * d1 * 2)};
    cuuint32_t box[3]     = {64u, 128u, 1u};
    cuuint32_t es[3]      = {1u, 1u, 1u};
    get_encode_fn()(tm, CU_TENSOR_MAP_DATA_TYPE_BFLOAT16, 3, base, dims, strides, box, es,
        CU_TENSOR_MAP_INTERLEAVE_NONE, CU_TENSOR_MAP_SWIZZLE_128B,
        CU_TENSOR_MAP_L2_PROMOTION_L2_128B, CU_TENSOR_MAP_FLOAT_OOB_FILL_NONE);
}

// ---------------- host launcher ----------------
extern "C" void kernel_launch(void* const* d_in, const int* in_sizes, int n_in,
                              void* d_out, int out_size) {
    const float* x        = (const float*)d_in[0];
    const float* x0       = (const float*)d_in[1];
    const float* noise    = (const float*)d_in[2];
    const float* lambdas  = (const float*)d_in[3];
    const float* qkv_w    = (const float*)d_in[5];
    const float* c_proj_w = (const float*)d_in[6];
    const float* c_proj_b = (const float*)d_in[7];
    const float* router_w = (const float*)d_in[8];
    const float* router_b = (const float*)d_in[9];
    const float* noise_w  = (const float*)d_in[10];
    const float* noise_b  = (const float*)d_in[11];
    const float* ew1      = (const float*)d_in[12];
    const float* eb1      = (const float*)d_in[13];
    const float* ew2      = (const float*)d_in[14];
    const float* eb2      = (const float*)d_in[15];
    float* out = (float*)d_out;

    void *p_xmix, *p_h, *p_idx, *p_cnt, *p_g0;
    void *p_abf, *p_obf, *p_hbf, *p_h1bf, *p_wqkv, *p_wcp, *p_we1, *p_we2;
    cudaGetSymbolAddress(&p_xmix, g_xmix);
    cudaGetSymbolAddress(&p_h,    g_h);
    cudaGetSymbolAddress(&p_idx,  g_idx);
    cudaGetSymbolAddress(&p_cnt,  g_cnt);
    cudaGetSymbolAddress(&p_g0,   g_g0);
    cudaGetSymbolAddress(&p_abf,  g_abf);
    cudaGetSymbolAddress(&p_obf,  g_obf);
    cudaGetSymbolAddress(&p_hbf,  g_hbf);
    cudaGetSymbolAddress(&p_h1bf, g_h1bf);
    cudaGetSymbolAddress(&p_wqkv, g_wqkv);
    cudaGetSymbolAddress(&p_wcp,  g_wcp);
    cudaGetSymbolAddress(&p_we1,  g_we1);
    cudaGetSymbolAddress(&p_we2,  g_we2);

    bf16* abf_h  = (bf16*)p_abf;   bf16* abf_l  = abf_h  + (size_t)NTOK*CC;
    bf16* obf_h  = (bf16*)p_obf;   bf16* obf_l  = obf_h  + (size_t)NTOK*CC;
    bf16* hbf_h  = (bf16*)p_hbf;   bf16* hbf_l  = hbf_h  + (size_t)NTOK*CC;
    bf16* h1_h   = (bf16*)p_h1bf;  bf16* h1_l   = h1_h   + (size_t)EE*CAPX*HID;
    bf16* wqkv_h = (bf16*)p_wqkv;  bf16* wqkv_l = wqkv_h + (size_t)3*CC*CC;
    bf16* wcp_h  = (bf16*)p_wcp;   bf16* wcp_l  = wcp_h  + (size_t)CC*CC;
    bf16* we1_h  = (bf16*)p_we1;   bf16* we1_l  = we1_h  + (size_t)EE*HID*CC;
    bf16* we2_h  = (bf16*)p_we2;   bf16* we2_l  = we2_h  + (size_t)EE*CC*HID;

    CUtensorMap tmQh, tmQl, tmCh, tmCl, tmE1h, tmE1l, tmE2h, tmE2l;
    mk_map(&tmQh,  wqkv_h, CC, CC, 3);
    mk_map(&tmQl,  wqkv_l, CC, CC, 3);
    mk_map(&tmCh,  wcp_h,  CC, CC, 1);
    mk_map(&tmCl,  wcp_l,  CC, CC, 1);
    mk_map(&tmE1h, we1_h,  CC, HID, EE);
    mk_map(&tmE1l, we1_l,  CC, HID, EE);
    mk_map(&tmE2h, we2_h,  HID, CC, EE);
    mk_map(&tmE2l, we2_l,  HID, CC, EE);

    cudaFuncSetAttribute(gemm_bf<5,false,false>, cudaFuncAttributeMaxDynamicSharedMemorySize, SMEM_TOTAL_TC);
    cudaFuncSetAttribute(gemm_bf<2,false,false>, cudaFuncAttributeMaxDynamicSharedMemorySize, SMEM_TOTAL_TC);
    cudaFuncSetAttribute(gemm_bf<3,true, true >, cudaFuncAttributeMaxDynamicSharedMemorySize, SMEM_TOTAL_TC);
    cudaFuncSetAttribute(gemm_bf<4,false,true >, cudaFuncAttributeMaxDynamicSharedMemorySize, SMEM_TOTAL_TC);
    cudaFuncSetAttribute(attn_tc, cudaFuncAttributeMaxDynamicSharedMemorySize, SMEM_ATT);

    // launch configs: cluster GEMM (cluster + PDL), plain PDL
    cudaLaunchAttribute gattr[2];
    gattr[0].id = cudaLaunchAttributeClusterDimension;
    gattr[0].val.clusterDim.x = 1; gattr[0].val.clusterDim.y = 2; gattr[0].val.clusterDim.z = 1;
    gattr[1].id = cudaLaunchAttributeProgrammaticStreamSerialization;
    gattr[1].val.programmaticStreamSerializationAllowed = 1;
    cudaLaunchConfig_t gcfg = {};
    gcfg.blockDim = dim3(256, 1, 1);
    gcfg.dynamicSmemBytes = SMEM_TOTAL_TC;
    gcfg.attrs = gattr;
    gcfg.numAttrs = 2;
    gcfg.stream = 0;

    cudaLaunchAttribute pattr[1];
    pattr[0].id = cudaLaunchAttributeProgrammaticStreamSerialization;
    pattr[0].val.programmaticStreamSerializationAllowed = 1;
    cudaLaunchConfig_t pcfg = {};
    pcfg.attrs = pattr;
    pcfg.numAttrs = 1;
    pcfg.stream = 0;

    // ---- side stream: rotary tables + deferred weight conversions
    cudaStream_t s2;
    cudaStreamCreateWithFlags(&s2, cudaStreamNonBlocking);
    cudaEvent_t evFork, evRot, evJoinCp, evJoinMoE;
    cudaEventCreateWithFlags(&evFork,    cudaEventDisableTiming);
    cudaEventCreateWithFlags(&evRot,     cudaEventDisableTiming);
    cudaEventCreateWithFlags(&evJoinCp,  cudaEventDisableTiming);
    cudaEventCreateWithFlags(&evJoinMoE, cudaEventDisableTiming);

    cudaEventRecord(evFork, 0);
    cudaStreamWaitEvent(s2, evFork, 0);

    rot_tab_kernel<<<(TT*16 + 255)/256, 256, 0, s2>>>();
    cudaEventRecord(evRot, s2);
    conv_kernel<<<(CC*CC/4 + 255)/256, 256, 0, s2>>>(c_proj_w, wcp_h, wcp_l, (long)CC*CC/4);
    cudaEventRecord(evJoinCp, s2);
    conv_kernel<<<((long)EE*HID*CC/4 + 255)/256, 256, 0, s2>>>(ew1, we1_h, we1_l, (long)EE*HID*CC/4);
    conv_kernel<<<((long)EE*CC*HID/4 + 255)/256, 256, 0, s2>>>(ew2, we2_h, we2_l, (long)EE*CC*HID/4);
    cudaEventRecord(evJoinMoE, s2);

    // main: qkv weight conv + pipeline
    conv_kernel<<<(3*CC*CC/4 + 255)/256, 256>>>(qkv_w, wqkv_h, wqkv_l, (long)3*CC*CC/4);

    pcfg.gridDim = dim3(NTOK, 1, 1);
    pcfg.blockDim = dim3(256, 1, 1);
    pcfg.dynamicSmemBytes = 0;
    cudaLaunchKernelEx(&pcfg, mix_rms_kernel, x, x0, lambdas);

    cudaStreamWaitEvent(0, evRot, 0);   // rot tables ready before qkv epilogue

    gcfg.gridDim = dim3(CC/256, NTOK/128, 3);
    cudaLaunchKernelEx(&gcfg, gemm_bf<5,false,false>,
        (const bf16*)abf_h, (const bf16*)abf_l, 0L,
        (const bf16*)wqkv_h, (const bf16*)wqkv_l, (long)CC*CC,
        tmQh, tmQl,
        (float*)nullptr, (bf16*)nullptr, (bf16*)nullptr, 0L,
        (const float*)nullptr, 0, (const float*)nullptr,
        (const int*)nullptr, (const int*)nullptr, (const float*)nullptr, (int)CC, (int)CC);

    pcfg.gridDim = dim3(TT/128, 2*HH, 1);
    pcfg.blockDim = dim3(256, 1, 1);
    pcfg.dynamicSmemBytes = SMEM_ATT;
    cudaLaunchKernelEx(&pcfg, attn_tc);

    cudaStreamWaitEvent(0, evJoinCp, 0);
    gcfg.gridDim = dim3(CC/256, NTOK/128, 1);
    cudaLaunchKernelEx(&gcfg, gemm_bf<2,false,false>,
        (const bf16*)obf_h, (const bf16*)obf_l, 0L,
        (const bf16*)wcp_h, (const bf16*)wcp_l, 0L,
        tmCh, tmCl,
        out, (bf16*)nullptr, (bf16*)nullptr, 0L,
        c_proj_b, 0, (const float*)p_xmix,
        (const int*)nullptr, (const int*)nullptr, (const float*)nullptr, (int)CC, (int)CC);

    pcfg.gridDim = dim3(NTOK, 1, 1);
    pcfg.blockDim = dim3(256, 1, 1);
    pcfg.dynamicSmemBytes = 0;
    cudaLaunchKernelEx(&pcfg, rms2_kernel, (const float*)out);

    cudaLaunchKernelEx(&pcfg, router_kernel, router_w, router_b, noise_w, noise_b, noise);

    pcfg.gridDim = dim3(1, 1, 1);
    cudaLaunchKernelEx(&pcfg, build_idx_kernel);

    cudaStreamWaitEvent(0, evJoinMoE, 0);

    gcfg.gridDim = dim3(HID/256, CAPX/128, EE);
    cudaLaunchKernelEx(&gcfg, gemm_bf<3,true,true>,
        (const bf16*)hbf_h, (const bf16*)hbf_l, 0L,
        (const bf16*)we1_h, (const bf16*)we1_l, (long)HID*CC,
        tmE1h, tmE1l,
        (float*)nullptr, h1_h, h1_l, (long)CAPX*HID,
        eb1, (int)HID, (const float*)nullptr,
        (const int*)p_idx, (const int*)p_cnt, (const float*)nullptr, (int)HID, (int)CC);

    gcfg.gridDim = dim3(CC/256, CAPX/128, EE);
    cudaLaunchKernelEx(&gcfg, gemm_bf<4,false,true>,
        (const bf16*)h1_h, (const bf16*)h1_l, (long)CAPX*HID,
        (const bf16*)we2_h, (const bf16*)we2_l, (long)CC*HID,
        tmE2h, tmE2l,
        out, (bf16*)nullptr, (bf16*)nullptr, 0L,
        eb2, (int)CC, (const float*)nullptr,
        (const int*)p_idx, (const int*)p_cnt, (const float*)p_g0, (int)CC, (int)HID);

    cudaEventDestroy(evFork);
    cudaEventDestroy(evRot);
    cudaEventDestroy(evJoinCp);
    cudaEventDestroy(evJoinMoE);
    cudaStreamDestroy(s2);
}